// round 3
// baseline (speedup 1.0000x reference)
#include <cuda_runtime.h>
#include <cuda_bf16.h>
#include <cstddef>

// ---------------------------------------------------------------------------
// DepthAwareBokehDFN: conv1(4->64)+relu, conv2(64->64)+relu, conv3(64->81),
// softmax over 81 taps, 9x9 dynamic-filter bokeh on RGB.
// B=4, H=W=384, exact fp32; packed fma.rn.f32x2 inner loops.
// R3 fix: conv3 epilogue half-column guard (write race on channels 42/43).
// ---------------------------------------------------------------------------

#define HH 384
#define WW 384
#define BATCH 4
#define HWSZ (HH * WW)

// Scratch (device globals: allocation-free per harness rules)
__device__ float g_h1[(size_t)BATCH * 64 * HWSZ];
__device__ float g_h2[(size_t)BATCH * 64 * HWSZ];
__device__ float g_logits[(size_t)BATCH * 81 * HWSZ];

// ---- packed f32x2 helpers --------------------------------------------------
__device__ __forceinline__ unsigned long long pack2(float x, float y) {
    unsigned long long r;
    asm("mov.b64 %0, {%1, %2};" : "=l"(r) : "f"(x), "f"(y));
    return r;
}
__device__ __forceinline__ unsigned long long bcast2(float x) { return pack2(x, x); }
__device__ __forceinline__ float2 unpack2(unsigned long long v) {
    float2 f;
    asm("mov.b64 {%0, %1}, %2;" : "=f"(f.x), "=f"(f.y) : "l"(v));
    return f;
}
__device__ __forceinline__ unsigned long long ffma2(unsigned long long a,
                                                    unsigned long long b,
                                                    unsigned long long c) {
    unsigned long long d;
    asm("fma.rn.f32x2 %0, %1, %2, %3;" : "=l"(d) : "l"(a), "l"(b), "l"(c));
    return d;
}

// ---------------------------------------------------------------------------
// Direct 3x3 conv, SAME padding, stride 1.
// Block: 256 threads = 32 lanes (x) * 4 (y) * 2 (channel half).
// Each thread: 2 pixels (y, y+4) x (CO_TP) channels, packed-pair accumulators.
// Weights staged in SMEM per CCH input-channel chunk, zero-padded layout
// ws[CCH][9][2][CO_TP] so both channel halves are 16B aligned.
// ---------------------------------------------------------------------------
template <int CIN, int COUT, int CO_HALF, int CO_TP, int CCH, bool RELU, bool CONCAT>
__global__ __launch_bounds__(256, 2)
void conv3x3_kernel(const float* __restrict__ in0, const float* __restrict__ in1,
                    const float* __restrict__ wgt, const float* __restrict__ bias,
                    float* __restrict__ out) {
    static_assert(CO_TP % 4 == 0, "pairs must allow ull2 loads");
    constexpr int NP  = CO_TP / 2;   // u64 channel-pairs per thread
    constexpr int NP2 = NP / 2;      // ulonglong2 loads per tap
    static_assert(NP % 2 == 0, "NP must be even");

    __shared__ __align__(16) float ws[CCH][9][2][CO_TP];

    const int tid = threadIdx.x;
    const int lx  = tid & 31;
    const int ty  = (tid >> 5) & 3;
    const int tz  = tid >> 7;            // 0 or 1: channel half
    const int x   = blockIdx.x * 32 + lx;
    const int y0  = blockIdx.y * 8 + ty; // pixel 0; pixel 1 = y0+4
    const int b   = blockIdx.z;
    const int co_base = tz * CO_HALF;

    unsigned long long acc[2][NP];
#pragma unroll
    for (int p = 0; p < NP; p++) {
        int co = co_base + 2 * p;
        float bv0 = (co     < COUT) ? bias[co]     : 0.f;
        float bv1 = (co + 1 < COUT) ? bias[co + 1] : 0.f;
        unsigned long long bb = pack2(bv0, bv1);
        acc[0][p] = bb;
        acc[1][p] = bb;
    }

    for (int ci0 = 0; ci0 < CIN; ci0 += CCH) {
        __syncthreads();
        // cooperative weight stage (zero-pad beyond real channels)
        constexpr int TOT = CCH * 9 * 2 * CO_TP;
        for (int i = tid; i < TOT; i += 256) {
            int cop = i % (2 * CO_TP);
            int t   = (i / (2 * CO_TP)) % 9;
            int cl  = i / (2 * CO_TP * 9);
            int tzz = cop / CO_TP;
            int col = cop % CO_TP;
            int cog = tzz * CO_HALF + col;
            float wv = 0.f;
            if (col < CO_HALF && cog < COUT)
                wv = wgt[((size_t)cog * CIN + (ci0 + cl)) * 9 + t];
            (&ws[0][0][0][0])[i] = wv;
        }
        __syncthreads();

#pragma unroll 1
        for (int cl = 0; cl < CCH; cl++) {
            const int ci = ci0 + cl;
            const float* ip;
            if (CONCAT)
                ip = (ci < 3) ? (in0 + ((size_t)b * 3 + ci) * HWSZ)
                              : (in1 + (size_t)b * HWSZ);
            else
                ip = in0 + ((size_t)b * CIN + ci) * HWSZ;

            float v[2][9];
#pragma unroll
            for (int pp = 0; pp < 2; pp++) {
                int yb = y0 + pp * 4;
#pragma unroll
                for (int dy = -1; dy <= 1; dy++) {
                    int yy = yb + dy;
                    bool yok = (yy >= 0) && (yy < HH);
#pragma unroll
                    for (int dx = -1; dx <= 1; dx++) {
                        int xx = x + dx;
                        bool ok = yok && (xx >= 0) && (xx < WW);
                        v[pp][(dy + 1) * 3 + (dx + 1)] =
                            ok ? __ldg(ip + (size_t)yy * WW + xx) : 0.f;
                    }
                }
            }

#pragma unroll
            for (int t = 0; t < 9; t++) {
                unsigned long long v0 = bcast2(v[0][t]);
                unsigned long long v1 = bcast2(v[1][t]);
                const ulonglong2* wp2 =
                    reinterpret_cast<const ulonglong2*>(&ws[cl][t][tz][0]);
#pragma unroll
                for (int q = 0; q < NP2; q++) {
                    ulonglong2 wq = wp2[q];
                    acc[0][2 * q]     = ffma2(v0, wq.x, acc[0][2 * q]);
                    acc[1][2 * q]     = ffma2(v1, wq.x, acc[1][2 * q]);
                    acc[0][2 * q + 1] = ffma2(v0, wq.y, acc[0][2 * q + 1]);
                    acc[1][2 * q + 1] = ffma2(v1, wq.y, acc[1][2 * q + 1]);
                }
            }
        }
    }

    // epilogue: guard on BOTH the per-half padded column (2p < CO_HALF) and
    // the global channel (co < COUT) — prevents tz=0's zero-weight padded
    // columns from racing with tz=1's real channels.
#pragma unroll
    for (int pp = 0; pp < 2; pp++) {
        int yy = y0 + pp * 4;
#pragma unroll
        for (int p = 0; p < NP; p++) {
            float2 f = unpack2(acc[pp][p]);
            if (RELU) { f.x = fmaxf(f.x, 0.f); f.y = fmaxf(f.y, 0.f); }
            int co = co_base + 2 * p;
            size_t base = ((size_t)b * COUT) * HWSZ + (size_t)yy * WW + x;
            if (2 * p     < CO_HALF && co     < COUT) out[base + (size_t)co * HWSZ]       = f.x;
            if (2 * p + 1 < CO_HALF && co + 1 < COUT) out[base + (size_t)(co + 1) * HWSZ] = f.y;
        }
    }
}

// ---------------------------------------------------------------------------
// Fused softmax(81) + 9x9 dynamic-filter bokeh.
// Block: 128 threads = 32x4 pixel tile; RGB patch halo staged in SMEM.
// ---------------------------------------------------------------------------
__global__ __launch_bounds__(128, 4)
void softmax_bokeh_kernel(const float* __restrict__ logits,
                          const float* __restrict__ rgb,
                          float* __restrict__ out) {
    __shared__ float tile[3][12][40];  // (4+8) x (32+8) halo tile per color

    const int tid = threadIdx.x;
    const int lx  = tid & 31;
    const int ty  = tid >> 5;
    const int x   = blockIdx.x * 32 + lx;
    const int y   = blockIdx.y * 4 + ty;
    const int b   = blockIdx.z;
    const int gx0 = blockIdx.x * 32 - 4;
    const int gy0 = blockIdx.y * 4 - 4;

    for (int i = tid; i < 3 * 12 * 40; i += 128) {
        int xx = i % 40;
        int yy = (i / 40) % 12;
        int c  = i / 480;
        int gx = gx0 + xx, gy = gy0 + yy;
        float v = 0.f;
        if (gx >= 0 && gx < WW && gy >= 0 && gy < HH)
            v = rgb[((size_t)b * 3 + c) * HWSZ + (size_t)gy * WW + gx];
        tile[c][yy][xx] = v;
    }
    __syncthreads();

    float lg[81];
    const float* lp = logits + (size_t)b * 81 * HWSZ + (size_t)y * WW + x;
    float m = -1e30f;
#pragma unroll
    for (int t = 0; t < 81; t++) {
        lg[t] = __ldg(lp + (size_t)t * HWSZ);
        m = fmaxf(m, lg[t]);
    }
    float s = 0.f;
#pragma unroll
    for (int t = 0; t < 81; t++) {
        float e = __expf(lg[t] - m);
        lg[t] = e;
        s += e;
    }
    float inv = 1.f / s;

    float r = 0.f, g = 0.f, bl = 0.f;
#pragma unroll
    for (int dy = 0; dy < 9; dy++) {
#pragma unroll
        for (int dx = 0; dx < 9; dx++) {
            float f = lg[dy * 9 + dx] * inv;
            int sy = ty + dy;
            int sx = lx + dx;
            r  += f * tile[0][sy][sx];
            g  += f * tile[1][sy][sx];
            bl += f * tile[2][sy][sx];
        }
    }

    size_t ob = (size_t)b * 3 * HWSZ + (size_t)y * WW + x;
    out[ob]              = r;
    out[ob + HWSZ]       = g;
    out[ob + 2 * HWSZ]   = bl;
}

// ---------------------------------------------------------------------------
extern "C" void kernel_launch(void* const* d_in, const int* in_sizes, int n_in,
                              void* d_out, int out_size) {
    const float* rgb   = (const float*)d_in[0];
    const float* depth = (const float*)d_in[1];
    const float* w1    = (const float*)d_in[2];
    const float* b1    = (const float*)d_in[3];
    const float* w2    = (const float*)d_in[4];
    const float* b2    = (const float*)d_in[5];
    const float* w3    = (const float*)d_in[6];
    const float* b3    = (const float*)d_in[7];
    float* out = (float*)d_out;

    float *h1, *h2, *lg;
    cudaGetSymbolAddress((void**)&h1, g_h1);
    cudaGetSymbolAddress((void**)&h2, g_h2);
    cudaGetSymbolAddress((void**)&lg, g_logits);

    dim3 blk(256);
    dim3 grd(WW / 32, HH / 8, BATCH);

    // conv1: 4 -> 64, relu, concat(rgb, depth)
    conv3x3_kernel<4, 64, 32, 32, 4, true, true><<<grd, blk>>>(rgb, depth, w1, b1, h1);
    // conv2: 64 -> 64, relu
    conv3x3_kernel<64, 64, 32, 32, 16, true, false><<<grd, blk>>>(h1, nullptr, w2, b2, h2);
    // conv3: 64 -> 81 (padded to 2x44)
    conv3x3_kernel<64, 81, 42, 44, 8, false, false><<<grd, blk>>>(h2, nullptr, w3, b3, lg);
    // softmax + bokeh
    softmax_bokeh_kernel<<<dim3(WW / 32, HH / 4, BATCH), dim3(128)>>>(lg, rgb, out);
}

// round 4
// speedup vs baseline: 1.0472x; 1.0472x over previous
#include <cuda_runtime.h>
#include <cuda_bf16.h>
#include <cstddef>

// ---------------------------------------------------------------------------
// DepthAwareBokehDFN: conv1(4->64)+relu, conv2(64->64)+relu, conv3(64->81),
// softmax over 81 taps, 9x9 dynamic-filter bokeh on RGB.
// B=4, H=W=384, exact fp32; packed fma.rn.f32x2 inner loops.
// R4: y-adjacent pixel blocking (shared halo LDG + weight-LDS reuse across
// PIX pixels), 512-thread blocks, 4 output-channel quarters.
// ---------------------------------------------------------------------------

#define HH 384
#define WW 384
#define BATCH 4
#define HWSZ (HH * WW)

// Scratch (device globals: allocation-free per harness rules)
__device__ float g_h1[(size_t)BATCH * 64 * HWSZ];
__device__ float g_h2[(size_t)BATCH * 64 * HWSZ];
__device__ float g_logits[(size_t)BATCH * 81 * HWSZ];

// ---- packed f32x2 helpers --------------------------------------------------
__device__ __forceinline__ unsigned long long pack2(float x, float y) {
    unsigned long long r;
    asm("mov.b64 %0, {%1, %2};" : "=l"(r) : "f"(x), "f"(y));
    return r;
}
__device__ __forceinline__ unsigned long long bcast2(float x) { return pack2(x, x); }
__device__ __forceinline__ float2 unpack2(unsigned long long v) {
    float2 f;
    asm("mov.b64 {%0, %1}, %2;" : "=f"(f.x), "=f"(f.y) : "l"(v));
    return f;
}
__device__ __forceinline__ unsigned long long ffma2(unsigned long long a,
                                                    unsigned long long b,
                                                    unsigned long long c) {
    unsigned long long d;
    asm("fma.rn.f32x2 %0, %1, %2, %3;" : "=l"(d) : "l"(a), "l"(b), "l"(c));
    return d;
}

// ---------------------------------------------------------------------------
// Direct 3x3 conv, SAME padding, stride 1.
// Block: 512 threads = 32 lanes (x) * 4 (ty: y groups) * 4 (q: channel quarter).
// Each thread: PIX y-adjacent pixels x CO_TP output channels.
// The PIX 3x3 windows overlap: (PIX+2) rows x 3 columns of input serve all
// taps, and each weight LDS feeds PIX pixels.
// Weights staged in SMEM per CCH input-channel chunk, zero-padded layout
// ws[CCH][9][NQ][CO_TP]; quarter q owns output channels [q*QS, q*QS+QS).
// ---------------------------------------------------------------------------
template <int CIN, int COUT, int NQ, int QS, int CO_TP, int PIX, int CCH,
          bool RELU, bool CONCAT>
__global__ __launch_bounds__(512, 1)
void conv3x3_v2(const float* __restrict__ in0, const float* __restrict__ in1,
                const float* __restrict__ wgt, const float* __restrict__ bias,
                float* __restrict__ out) {
    constexpr int NP  = CO_TP / 2;   // u64 channel-pairs per thread
    constexpr int NP2 = NP / 2;      // ulonglong2 loads per tap
    static_assert(CO_TP % 4 == 0, "CO_TP must be a multiple of 4");
    static_assert(NQ == 4, "block layout assumes 4 quarters");

    __shared__ __align__(16) float ws[CCH][9][NQ][CO_TP];

    const int tid = threadIdx.x;
    const int lx  = tid & 31;
    const int ty  = (tid >> 5) & 3;
    const int q   = tid >> 7;                  // 0..3 channel quarter
    const int x   = blockIdx.x * 32 + lx;
    const int y0  = blockIdx.y * (4 * PIX) + ty * PIX;
    const int b   = blockIdx.z;
    const int co0 = q * QS;

    unsigned long long acc[PIX][NP];
#pragma unroll
    for (int pr = 0; pr < NP; pr++) {
        int co = co0 + 2 * pr;
        float bv0 = (co     < COUT) ? __ldg(bias + co)     : 0.f;
        float bv1 = (co + 1 < COUT) ? __ldg(bias + co + 1) : 0.f;
        unsigned long long bb = pack2(bv0, bv1);
#pragma unroll
        for (int p = 0; p < PIX; p++) acc[p][pr] = bb;
    }

    // ci-invariant row offsets / validity
    int  rowoff[PIX + 2];
    bool rok[PIX + 2];
#pragma unroll
    for (int r = 0; r < PIX + 2; r++) {
        int yy = y0 - 1 + r;
        rok[r] = (yy >= 0) && (yy < HH);
        rowoff[r] = yy * WW;
    }
    const bool xok0 = (x > 0);
    const bool xok2 = (x < WW - 1);

    for (int ci0 = 0; ci0 < CIN; ci0 += CCH) {
        __syncthreads();
        // cooperative weight stage (zero-pad beyond real channels)
        constexpr int TOT = CCH * 9 * NQ * CO_TP;
        for (int i = tid; i < TOT; i += 512) {
            int col = i % CO_TP;
            int qq  = (i / CO_TP) % NQ;
            int t   = (i / (CO_TP * NQ)) % 9;
            int cl  = i / (CO_TP * NQ * 9);
            int cog = qq * QS + col;
            float wv = 0.f;
            if (col < QS && cog < COUT)
                wv = __ldg(wgt + ((size_t)cog * CIN + (ci0 + cl)) * 9 + t);
            (&ws[0][0][0][0])[i] = wv;
        }
        __syncthreads();

#pragma unroll 1
        for (int cl = 0; cl < CCH; cl++) {
            const int ci = ci0 + cl;
            const float* ip;
            if (CONCAT)
                ip = (ci < 3) ? (in0 + ((size_t)b * 3 + ci) * HWSZ)
                              : (in1 + (size_t)b * HWSZ);
            else
                ip = in0 + ((size_t)b * CIN + ci) * HWSZ;
            const float* ipx = ip + x;

            float v[PIX + 2][3];
#pragma unroll
            for (int r = 0; r < PIX + 2; r++) {
                v[r][0] = (rok[r] && xok0) ? __ldg(ipx + rowoff[r] - 1) : 0.f;
                v[r][1] =  rok[r]          ? __ldg(ipx + rowoff[r])     : 0.f;
                v[r][2] = (rok[r] && xok2) ? __ldg(ipx + rowoff[r] + 1) : 0.f;
            }

#pragma unroll
            for (int dy = 0; dy < 3; dy++) {
#pragma unroll
                for (int dx = 0; dx < 3; dx++) {
                    const int t = dy * 3 + dx;
                    const ulonglong2* wp =
                        reinterpret_cast<const ulonglong2*>(&ws[cl][t][q][0]);
                    ulonglong2 wq[NP2];
#pragma unroll
                    for (int j = 0; j < NP2; j++) wq[j] = wp[j];
#pragma unroll
                    for (int p = 0; p < PIX; p++) {
                        unsigned long long vv = bcast2(v[p + dy][dx]);
#pragma unroll
                        for (int j = 0; j < NP2; j++) {
                            acc[p][2 * j]     = ffma2(vv, wq[j].x, acc[p][2 * j]);
                            acc[p][2 * j + 1] = ffma2(vv, wq[j].y, acc[p][2 * j + 1]);
                        }
                    }
                }
            }
        }
    }

    // epilogue: guard per-quarter padded columns AND global channel count
#pragma unroll
    for (int p = 0; p < PIX; p++) {
        int yy = y0 + p;
        size_t base = ((size_t)b * COUT) * HWSZ + (size_t)yy * WW + x;
#pragma unroll
        for (int pr = 0; pr < NP; pr++) {
            float2 f = unpack2(acc[p][pr]);
            if (RELU) { f.x = fmaxf(f.x, 0.f); f.y = fmaxf(f.y, 0.f); }
            int co = co0 + 2 * pr;
            if (2 * pr     < QS && co     < COUT) out[base + (size_t)co * HWSZ]       = f.x;
            if (2 * pr + 1 < QS && co + 1 < COUT) out[base + (size_t)(co + 1) * HWSZ] = f.y;
        }
    }
}

// ---------------------------------------------------------------------------
// Fused softmax(81) + 9x9 dynamic-filter bokeh.
// Block: 128 threads = 32x4 pixel tile; RGB patch halo staged in SMEM.
// ---------------------------------------------------------------------------
__global__ __launch_bounds__(128, 4)
void softmax_bokeh_kernel(const float* __restrict__ logits,
                          const float* __restrict__ rgb,
                          float* __restrict__ out) {
    __shared__ float tile[3][12][40];  // (4+8) x (32+8) halo tile per color

    const int tid = threadIdx.x;
    const int lx  = tid & 31;
    const int ty  = tid >> 5;
    const int x   = blockIdx.x * 32 + lx;
    const int y   = blockIdx.y * 4 + ty;
    const int b   = blockIdx.z;
    const int gx0 = blockIdx.x * 32 - 4;
    const int gy0 = blockIdx.y * 4 - 4;

    for (int i = tid; i < 3 * 12 * 40; i += 128) {
        int xx = i % 40;
        int yy = (i / 40) % 12;
        int c  = i / 480;
        int gx = gx0 + xx, gy = gy0 + yy;
        float v = 0.f;
        if (gx >= 0 && gx < WW && gy >= 0 && gy < HH)
            v = rgb[((size_t)b * 3 + c) * HWSZ + (size_t)gy * WW + gx];
        tile[c][yy][xx] = v;
    }
    __syncthreads();

    float lg[81];
    const float* lp = logits + (size_t)b * 81 * HWSZ + (size_t)y * WW + x;
    float m = -1e30f;
#pragma unroll
    for (int t = 0; t < 81; t++) {
        lg[t] = __ldg(lp + (size_t)t * HWSZ);
        m = fmaxf(m, lg[t]);
    }
    float s = 0.f;
#pragma unroll
    for (int t = 0; t < 81; t++) {
        float e = __expf(lg[t] - m);
        lg[t] = e;
        s += e;
    }
    float inv = 1.f / s;

    float r = 0.f, g = 0.f, bl = 0.f;
#pragma unroll
    for (int dy = 0; dy < 9; dy++) {
#pragma unroll
        for (int dx = 0; dx < 9; dx++) {
            float f = lg[dy * 9 + dx] * inv;
            int sy = ty + dy;
            int sx = lx + dx;
            r  += f * tile[0][sy][sx];
            g  += f * tile[1][sy][sx];
            bl += f * tile[2][sy][sx];
        }
    }

    size_t ob = (size_t)b * 3 * HWSZ + (size_t)y * WW + x;
    out[ob]              = r;
    out[ob + HWSZ]       = g;
    out[ob + 2 * HWSZ]   = bl;
}

// ---------------------------------------------------------------------------
extern "C" void kernel_launch(void* const* d_in, const int* in_sizes, int n_in,
                              void* d_out, int out_size) {
    const float* rgb   = (const float*)d_in[0];
    const float* depth = (const float*)d_in[1];
    const float* w1    = (const float*)d_in[2];
    const float* b1    = (const float*)d_in[3];
    const float* w2    = (const float*)d_in[4];
    const float* b2    = (const float*)d_in[5];
    const float* w3    = (const float*)d_in[6];
    const float* b3    = (const float*)d_in[7];
    float* out = (float*)d_out;

    float *h1, *h2, *lg;
    cudaGetSymbolAddress((void**)&h1, g_h1);
    cudaGetSymbolAddress((void**)&h2, g_h2);
    cudaGetSymbolAddress((void**)&lg, g_logits);

    dim3 blk(512);

    // conv1: 4 -> 64, relu, concat(rgb, depth). PIX=4 -> 16 rows/block.
    conv3x3_v2<4, 64, 4, 16, 16, 4, 4, true, true>
        <<<dim3(WW / 32, HH / 16, BATCH), blk>>>(rgb, depth, w1, b1, h1);
    // conv2: 64 -> 64, relu. PIX=4 -> 16 rows/block.
    conv3x3_v2<64, 64, 4, 16, 16, 4, 16, true, false>
        <<<dim3(WW / 32, HH / 16, BATCH), blk>>>(h1, nullptr, w2, b2, h2);
    // conv3: 64 -> 81 (4 quarters of 21, CO_TP=24 padded). PIX=3 -> 12 rows/block.
    conv3x3_v2<64, 81, 4, 21, 24, 3, 8, false, false>
        <<<dim3(WW / 32, HH / 12, BATCH), blk>>>(h2, nullptr, w3, b3, lg);
    // softmax + bokeh
    softmax_bokeh_kernel<<<dim3(WW / 32, HH / 4, BATCH), dim3(128)>>>(lg, rgb, out);
}

// round 6
// speedup vs baseline: 1.6203x; 1.5473x over previous
#include <cuda_runtime.h>
#include <cuda_bf16.h>
#include <cstdint>
#include <cstddef>

#define HH 384
#define WW 384
#define BATCH 4
#define HWSZ (HH * WW)

__device__ float g_h1[(size_t)BATCH * 64 * HWSZ];
__device__ float g_h2[(size_t)BATCH * 64 * HWSZ];
__device__ float g_logits[(size_t)BATCH * 81 * HWSZ];

// =============================== helpers ====================================
__device__ __forceinline__ uint32_t smem_u32(const void* p) {
    uint32_t a;
    asm("{ .reg .u64 t; cvta.to.shared.u64 t, %1; cvt.u32.u64 %0, t; }"
        : "=r"(a) : "l"(p));
    return a;
}
__device__ __forceinline__ void ldmx4(uint32_t& r0, uint32_t& r1, uint32_t& r2,
                                      uint32_t& r3, uint32_t addr) {
    asm volatile("ldmatrix.sync.aligned.m8n8.x4.shared.b16 {%0,%1,%2,%3}, [%4];"
                 : "=r"(r0), "=r"(r1), "=r"(r2), "=r"(r3) : "r"(addr));
}
__device__ __forceinline__ void mma16816(float* c, const uint32_t* a,
                                         uint32_t b0, uint32_t b1) {
    asm volatile(
        "mma.sync.aligned.m16n8k16.row.col.f32.bf16.bf16.f32 "
        "{%0,%1,%2,%3}, {%4,%5,%6,%7}, {%8,%9}, {%0,%1,%2,%3};"
        : "+f"(c[0]), "+f"(c[1]), "+f"(c[2]), "+f"(c[3])
        : "r"(a[0]), "r"(a[1]), "r"(a[2]), "r"(a[3]), "r"(b0), "r"(b1));
}
// pack two f32 -> bf16x2 (lo = f0), and residuals
__device__ __forceinline__ void split2(float f0, float f1, uint32_t& hi,
                                       uint32_t& lo) {
    asm("cvt.rn.bf16x2.f32 %0, %1, %2;" : "=r"(hi) : "f"(f1), "f"(f0));
    float f0h = __uint_as_float(hi << 16);
    float f1h = __uint_as_float(hi & 0xFFFF0000u);
    asm("cvt.rn.bf16x2.f32 %0, %1, %2;" : "=r"(lo) : "f"(f1 - f1h), "f"(f0 - f0h));
}

// ===================== HMMA implicit-GEMM 3x3 conv ==========================
// Per CTA: co-slice M=32, px-tile N=128, persist over RPC=32 output rows.
// A (weights, 9 taps, hi+lo) staged once; B (input) rolling 3 row-planes,
// layout [px][ci] bf16, 16B-chunk XOR swizzle; all taps = shifted views.
#define RPC 32
#define NPX 128
#define A_PLANE (9 * 32 * 128)                 // bytes per split
#define OFF_B   (2 * A_PLANE)                  // 73728
#define B_PLANE (132 * 128)                    // bytes per (split, slot)
#define HMMA_SMEM (OFF_B + 6 * B_PLANE)        // 175104

template <int COUT, int NSLICE, bool RELU>
__global__ __launch_bounds__(256, 1)
void conv3x3_hmma(const float* __restrict__ in, const float* __restrict__ wgt,
                  const float* __restrict__ bias, float* __restrict__ out) {
    extern __shared__ __align__(128) char smem[];
    const uint32_t sb = smem_u32(smem);
    const int tid = threadIdx.x, warp = tid >> 5, lane = tid & 31;
    const int x0 = blockIdx.x * NPX;
    const int y0 = blockIdx.y * RPC;
    const int mslice = blockIdx.z % NSLICE;
    const int b = blockIdx.z / NSLICE;
    const int co_base = mslice * 32;

    // ---- stage A: 9 taps x 32 co x 64 ci, hi+lo, swizzled [co][ci] ----
    {
        const int cpl = lane & 3, po = lane >> 2;  // 4 ci-pairs x 8 rows
        for (int it = warp; it < 288; it += 8) {   // 9 taps * 4 cotiles * 8 chunks
            int t = it / 32, r = it & 31;
            int cotile = r >> 3, c = r & 7;
            int co = cotile * 8 + po;
            int ci0 = c * 8 + cpl * 2;
            int cog = co_base + co;
            float f0 = 0.f, f1 = 0.f;
            if (cog < COUT) {
                const float* wp = wgt + ((size_t)cog * 64 + ci0) * 9 + t;
                f0 = __ldg(wp);
                f1 = __ldg(wp + 9);
            }
            uint32_t hi, lo;
            split2(f0, f1, hi, lo);
            uint32_t off = (uint32_t)((t * 32 + co) * 128 +
                                      ((c ^ (co & 7)) << 4) + cpl * 4);
            asm volatile("st.shared.b32 [%0], %1;" :: "r"(sb + off), "r"(hi) : "memory");
            asm volatile("st.shared.b32 [%0], %1;" :: "r"(sb + A_PLANE + off), "r"(lo) : "memory");
        }
    }

    // ---- B row-plane stage: row yy -> slot (yy+3)%3 ----
    auto stage_B = [&](int yy) {
        const int slot = (yy + 3) % 3;
        const bool ok_row = (yy >= 0) && (yy < HH);
        const float* src = in + ((size_t)b * 64 * HH + (ok_row ? yy : 0)) * WW;
        const int cpl = lane & 3, po = lane >> 2;
        const uint32_t bH = sb + OFF_B + slot * B_PLANE;
        const uint32_t bL = sb + OFF_B + (3 + slot) * B_PLANE;
        for (int it = warp; it < 136; it += 8) {  // 8 chunks * 17 px-tiles
            int c = it & 7, pxt = it >> 3;
            int px = pxt * 8 + po;
            if (px >= 132) continue;
            int ci0 = c * 8 + cpl * 2;
            int gx = x0 - 1 + px;
            bool ok = ok_row && (gx >= 0) && (gx < WW);
            const float* p = src + (size_t)ci0 * HWSZ + (ok ? gx : 0);
            float f0 = ok ? __ldg(p) : 0.f;
            float f1 = ok ? __ldg(p + HWSZ) : 0.f;
            uint32_t hi, lo;
            split2(f0, f1, hi, lo);
            uint32_t off = (uint32_t)(px * 128 + ((c ^ (px & 7)) << 4) + cpl * 4);
            asm volatile("st.shared.b32 [%0], %1;" :: "r"(bH + off), "r"(hi) : "memory");
            asm volatile("st.shared.b32 [%0], %1;" :: "r"(bL + off), "r"(lo) : "memory");
        }
    };

    stage_B(y0 - 1);
    stage_B(y0);
    stage_B(y0 + 1);
    __syncthreads();

    // lane decodes for ldmatrix addressing
    const int r7 = lane & 7, g = lane >> 3;
    const int a_row = r7 + ((g & 1) << 3);     // A: m0 r0-7/k0-7, m1 r8-15/k0-7, ...
    const int a_kh = g >> 1;
    const int b_noff = r7 + ((g >> 1) << 3);   // B: m0 n0-7/kh0, m1 n0-7/kh1, ...
    const int b_kh = g & 1;
    const int nb = warp * 16;

    const int yend = y0 + RPC;
#pragma unroll 1
    for (int y = y0; y < yend; y++) {
        float acc[4][4];
#pragma unroll
        for (int i = 0; i < 4; i++)
#pragma unroll
            for (int j = 0; j < 4; j++) acc[i][j] = 0.f;

        const int sl[3] = {(y + 2) % 3, (y + 3) % 3, (y + 4) % 3};

#pragma unroll 1
        for (int t = 0; t < 9; t++) {
            const int dy = t / 3, dx = t % 3;
            const uint32_t aH = sb + (uint32_t)(t * 32 * 128);
            const uint32_t aL = aH + A_PLANE;
            const uint32_t bHp = sb + OFF_B + sl[dy] * B_PLANE;
            const uint32_t bLp = bHp + 3 * B_PLANE;
            const int pxm = nb + dx + b_noff;
            const uint32_t bRow = (uint32_t)(pxm * 128);
            const int bx7 = pxm & 7;
#pragma unroll
            for (int kc = 0; kc < 4; kc++) {
                const uint32_t cA = (uint32_t)((((kc << 1) | a_kh) ^ r7) << 4);
                const uint32_t cB = (uint32_t)((((kc << 1) | b_kh) ^ bx7) << 4);
                uint32_t AH[2][4], AL[2][4], BH[4], BL[4];
                ldmx4(AH[0][0], AH[0][1], AH[0][2], AH[0][3],
                      aH + (uint32_t)(a_row * 128) + cA);
                ldmx4(AH[1][0], AH[1][1], AH[1][2], AH[1][3],
                      aH + (uint32_t)((a_row + 16) * 128) + cA);
                ldmx4(AL[0][0], AL[0][1], AL[0][2], AL[0][3],
                      aL + (uint32_t)(a_row * 128) + cA);
                ldmx4(AL[1][0], AL[1][1], AL[1][2], AL[1][3],
                      aL + (uint32_t)((a_row + 16) * 128) + cA);
                ldmx4(BH[0], BH[1], BH[2], BH[3], bHp + bRow + cB);
                ldmx4(BL[0], BL[1], BL[2], BL[3], bLp + bRow + cB);
#pragma unroll
                for (int mt = 0; mt < 2; mt++) {
#pragma unroll
                    for (int nt = 0; nt < 2; nt++) {
                        float* c = acc[mt * 2 + nt];
                        mma16816(c, AH[mt], BH[nt * 2], BH[nt * 2 + 1]);
                        mma16816(c, AH[mt], BL[nt * 2], BL[nt * 2 + 1]);
                        mma16816(c, AL[mt], BH[nt * 2], BH[nt * 2 + 1]);
                    }
                }
            }
        }

        // epilogue: D frag -> out, bias + relu
        {
            const int row_d = lane >> 2, col_d = (lane & 3) * 2;
#pragma unroll
            for (int mt = 0; mt < 2; mt++) {
#pragma unroll
                for (int nt = 0; nt < 2; nt++) {
                    float* c = acc[mt * 2 + nt];
                    int x = x0 + nb + nt * 8 + col_d;
#pragma unroll
                    for (int h = 0; h < 2; h++) {
                        int co = co_base + mt * 16 + row_d + h * 8;
                        if (co < COUT) {
                            float bv = __ldg(bias + co);
                            float v0 = c[2 * h] + bv, v1 = c[2 * h + 1] + bv;
                            if (RELU) { v0 = fmaxf(v0, 0.f); v1 = fmaxf(v1, 0.f); }
                            float2* op = reinterpret_cast<float2*>(
                                out + (((size_t)b * COUT + co) * HH + y) * WW + x);
                            *op = make_float2(v0, v1);
                        }
                    }
                }
            }
        }

        __syncthreads();
        if (y + 1 < yend) {
            stage_B(y + 2);
            __syncthreads();
        }
    }
}

// ======================= scalar conv1 (4 -> 64) =============================
__device__ __forceinline__ unsigned long long pack2(float x, float y) {
    unsigned long long r;
    asm("mov.b64 %0, {%1, %2};" : "=l"(r) : "f"(x), "f"(y));
    return r;
}
__device__ __forceinline__ unsigned long long bcast2(float x) { return pack2(x, x); }
__device__ __forceinline__ float2 unpack2(unsigned long long v) {
    float2 f;
    asm("mov.b64 {%0, %1}, %2;" : "=f"(f.x), "=f"(f.y) : "l"(v));
    return f;
}
__device__ __forceinline__ unsigned long long ffma2(unsigned long long a,
                                                    unsigned long long b,
                                                    unsigned long long c) {
    unsigned long long d;
    asm("fma.rn.f32x2 %0, %1, %2, %3;" : "=l"(d) : "l"(a), "l"(b), "l"(c));
    return d;
}

__global__ __launch_bounds__(512, 1)
void conv1_kernel(const float* __restrict__ rgb, const float* __restrict__ depth,
                  const float* __restrict__ wgt, const float* __restrict__ bias,
                  float* __restrict__ out) {
    constexpr int QS = 16, PIX = 4, CCH = 4;
    constexpr int NP = 8, NP2 = 4;
    __shared__ __align__(16) float ws[CCH][9][4][QS];

    const int tid = threadIdx.x;
    const int lx = tid & 31;
    const int ty = (tid >> 5) & 3;
    const int q = tid >> 7;
    const int x = blockIdx.x * 32 + lx;
    const int y0 = blockIdx.y * (4 * PIX) + ty * PIX;
    const int b = blockIdx.z;
    const int co0 = q * QS;

    unsigned long long acc[PIX][NP];
#pragma unroll
    for (int pr = 0; pr < NP; pr++) {
        unsigned long long bb = pack2(__ldg(bias + co0 + 2 * pr),
                                      __ldg(bias + co0 + 2 * pr + 1));
#pragma unroll
        for (int p = 0; p < PIX; p++) acc[p][pr] = bb;
    }

    int rowoff[PIX + 2];
    bool rok[PIX + 2];
#pragma unroll
    for (int r = 0; r < PIX + 2; r++) {
        int yy = y0 - 1 + r;
        rok[r] = (yy >= 0) && (yy < HH);
        rowoff[r] = yy * WW;
    }
    const bool xok0 = (x > 0), xok2 = (x < WW - 1);

    for (int i = tid; i < CCH * 9 * 4 * QS; i += 512) {
        int col = i % QS;
        int qq = (i / QS) % 4;
        int t = (i / (QS * 4)) % 9;
        int cl = i / (QS * 4 * 9);
        (&ws[0][0][0][0])[i] = __ldg(wgt + ((size_t)(qq * QS + col) * 4 + cl) * 9 + t);
    }
    __syncthreads();

#pragma unroll
    for (int ci = 0; ci < 4; ci++) {
        const float* ip = (ci < 3) ? (rgb + ((size_t)b * 3 + ci) * HWSZ)
                                   : (depth + (size_t)b * HWSZ);
        const float* ipx = ip + x;
        float v[PIX + 2][3];
#pragma unroll
        for (int r = 0; r < PIX + 2; r++) {
            v[r][0] = (rok[r] && xok0) ? __ldg(ipx + rowoff[r] - 1) : 0.f;
            v[r][1] = rok[r] ? __ldg(ipx + rowoff[r]) : 0.f;
            v[r][2] = (rok[r] && xok2) ? __ldg(ipx + rowoff[r] + 1) : 0.f;
        }
#pragma unroll
        for (int dy = 0; dy < 3; dy++) {
#pragma unroll
            for (int dx = 0; dx < 3; dx++) {
                const ulonglong2* wp =
                    reinterpret_cast<const ulonglong2*>(&ws[ci][dy * 3 + dx][q][0]);
                ulonglong2 wq[NP2];
#pragma unroll
                for (int j = 0; j < NP2; j++) wq[j] = wp[j];
#pragma unroll
                for (int p = 0; p < PIX; p++) {
                    unsigned long long vv = bcast2(v[p + dy][dx]);
#pragma unroll
                    for (int j = 0; j < NP2; j++) {
                        acc[p][2 * j] = ffma2(vv, wq[j].x, acc[p][2 * j]);
                        acc[p][2 * j + 1] = ffma2(vv, wq[j].y, acc[p][2 * j + 1]);
                    }
                }
            }
        }
    }

#pragma unroll
    for (int p = 0; p < PIX; p++) {
        size_t base = ((size_t)b * 64) * HWSZ + (size_t)(y0 + p) * WW + x;
#pragma unroll
        for (int pr = 0; pr < NP; pr++) {
            float2 f = unpack2(acc[p][pr]);
            f.x = fmaxf(f.x, 0.f);
            f.y = fmaxf(f.y, 0.f);
            int co = co0 + 2 * pr;
            out[base + (size_t)co * HWSZ] = f.x;
            out[base + (size_t)(co + 1) * HWSZ] = f.y;
        }
    }
}

// ======================= softmax + bokeh ====================================
__global__ __launch_bounds__(128, 4)
void softmax_bokeh_kernel(const float* __restrict__ logits,
                          const float* __restrict__ rgb,
                          float* __restrict__ out) {
    __shared__ float tile[3][12][40];
    const int tid = threadIdx.x;
    const int lx = tid & 31;
    const int ty = tid >> 5;
    const int x = blockIdx.x * 32 + lx;
    const int y = blockIdx.y * 4 + ty;
    const int b = blockIdx.z;
    const int gx0 = blockIdx.x * 32 - 4;
    const int gy0 = blockIdx.y * 4 - 4;

    for (int i = tid; i < 3 * 12 * 40; i += 128) {
        int xx = i % 40;
        int yy = (i / 40) % 12;
        int c = i / 480;
        int gx = gx0 + xx, gy = gy0 + yy;
        float v = 0.f;
        if (gx >= 0 && gx < WW && gy >= 0 && gy < HH)
            v = rgb[((size_t)b * 3 + c) * HWSZ + (size_t)gy * WW + gx];
        tile[c][yy][xx] = v;
    }
    __syncthreads();

    float lg[81];
    const float* lp = logits + (size_t)b * 81 * HWSZ + (size_t)y * WW + x;
    float m = -1e30f;
#pragma unroll
    for (int t = 0; t < 81; t++) {
        lg[t] = __ldg(lp + (size_t)t * HWSZ);
        m = fmaxf(m, lg[t]);
    }
    float s = 0.f;
#pragma unroll
    for (int t = 0; t < 81; t++) {
        float e = __expf(lg[t] - m);
        lg[t] = e;
        s += e;
    }
    float inv = 1.f / s;

    float r = 0.f, g = 0.f, bl = 0.f;
#pragma unroll
    for (int dy = 0; dy < 9; dy++) {
#pragma unroll
        for (int dx = 0; dx < 9; dx++) {
            float f = lg[dy * 9 + dx] * inv;
            r += f * tile[0][ty + dy][lx + dx];
            g += f * tile[1][ty + dy][lx + dx];
            bl += f * tile[2][ty + dy][lx + dx];
        }
    }
    size_t ob = (size_t)b * 3 * HWSZ + (size_t)y * WW + x;
    out[ob] = r;
    out[ob + HWSZ] = g;
    out[ob + 2 * HWSZ] = bl;
}

// ======================= launch =============================================
extern "C" void kernel_launch(void* const* d_in, const int* in_sizes, int n_in,
                              void* d_out, int out_size) {
    const float* rgb   = (const float*)d_in[0];
    const float* depth = (const float*)d_in[1];
    const float* w1    = (const float*)d_in[2];
    const float* b1    = (const float*)d_in[3];
    const float* w2    = (const float*)d_in[4];
    const float* b2    = (const float*)d_in[5];
    const float* w3    = (const float*)d_in[6];
    const float* b3    = (const float*)d_in[7];
    float* out = (float*)d_out;

    float *h1, *h2, *lg;
    cudaGetSymbolAddress((void**)&h1, g_h1);
    cudaGetSymbolAddress((void**)&h2, g_h2);
    cudaGetSymbolAddress((void**)&lg, g_logits);

    cudaFuncSetAttribute(conv3x3_hmma<64, 2, true>,
                         cudaFuncAttributeMaxDynamicSharedMemorySize, HMMA_SMEM);
    cudaFuncSetAttribute(conv3x3_hmma<81, 3, false>,
                         cudaFuncAttributeMaxDynamicSharedMemorySize, HMMA_SMEM);

    // conv1: scalar FFMA2
    conv1_kernel<<<dim3(WW / 32, HH / 16, BATCH), 512>>>(rgb, depth, w1, b1, h1);
    // conv2: HMMA implicit GEMM (2 co-slices of 32)
    conv3x3_hmma<64, 2, true><<<dim3(WW / NPX, HH / RPC, 2 * BATCH), 256,
                                HMMA_SMEM>>>(h1, w2, b2, h2);
    // conv3: HMMA implicit GEMM (3 co-slices of 32, 81 real channels)
    conv3x3_hmma<81, 3, false><<<dim3(WW / NPX, HH / RPC, 3 * BATCH), 256,
                                 HMMA_SMEM>>>(h2, w3, b3, lg);
    // softmax + bokeh
    softmax_bokeh_kernel<<<dim3(WW / 32, HH / 4, BATCH), 128>>>(lg, rgb, out);
}

// round 7
// speedup vs baseline: 1.6771x; 1.0350x over previous
#include <cuda_runtime.h>
#include <cuda_bf16.h>
#include <cstdint>
#include <cstddef>

#define HH 384
#define WW 384
#define BATCH 4
#define HWSZ (HH * WW)

// h1/h2 in split format: u32 = bf16(hi) | bf16(lo)<<16
__device__ uint32_t g_h1[(size_t)BATCH * 64 * HWSZ];
__device__ uint32_t g_h2[(size_t)BATCH * 64 * HWSZ];
__device__ float    g_logits[(size_t)BATCH * 81 * HWSZ];

// =============================== helpers ====================================
__device__ __forceinline__ uint32_t smem_u32(const void* p) {
    uint32_t a;
    asm("{ .reg .u64 t; cvta.to.shared.u64 t, %1; cvt.u32.u64 %0, t; }"
        : "=r"(a) : "l"(p));
    return a;
}
__device__ __forceinline__ void ldmx4(uint32_t& r0, uint32_t& r1, uint32_t& r2,
                                      uint32_t& r3, uint32_t addr) {
    asm volatile("ldmatrix.sync.aligned.m8n8.x4.shared.b16 {%0,%1,%2,%3}, [%4];"
                 : "=r"(r0), "=r"(r1), "=r"(r2), "=r"(r3) : "r"(addr));
}
__device__ __forceinline__ void mma16816(float* c, const uint32_t* a,
                                         uint32_t b0, uint32_t b1) {
    asm volatile(
        "mma.sync.aligned.m16n8k16.row.col.f32.bf16.bf16.f32 "
        "{%0,%1,%2,%3}, {%4,%5,%6,%7}, {%8,%9}, {%0,%1,%2,%3};"
        : "+f"(c[0]), "+f"(c[1]), "+f"(c[2]), "+f"(c[3])
        : "r"(a[0]), "r"(a[1]), "r"(a[2]), "r"(a[3]), "r"(b0), "r"(b1));
}
// pack two f32 -> bf16x2 (low half = f0), plus residual word
__device__ __forceinline__ void split2(float f0, float f1, uint32_t& hi,
                                       uint32_t& lo) {
    asm("cvt.rn.bf16x2.f32 %0, %1, %2;" : "=r"(hi) : "f"(f1), "f"(f0));
    float f0h = __uint_as_float(hi << 16);
    float f1h = __uint_as_float(hi & 0xFFFF0000u);
    asm("cvt.rn.bf16x2.f32 %0, %1, %2;" : "=r"(lo) : "f"(f1 - f1h), "f"(f0 - f0h));
}
// scalar split pack: u32 = bf16(v) | bf16(v - hi)<<16
__device__ __forceinline__ uint32_t pack_split(float v) {
    uint32_t h;
    asm("cvt.rn.bf16x2.f32 %0, %1, %1;" : "=r"(h) : "f"(v));
    float hf = __uint_as_float(h << 16);
    float l = v - hf;
    uint32_t lb;
    asm("cvt.rn.bf16x2.f32 %0, %1, %1;" : "=r"(lb) : "f"(l));
    return (h & 0xFFFFu) | (lb << 16);
}

// ===================== HMMA implicit-GEMM 3x3 conv ==========================
// Per CTA: co-slice M=32, px-tile N=128, persist over RPC=32 rows (2 per iter).
// A (weights, 9 taps, hi+lo) staged once; B (split-format input) ring of 4
// row-planes x {hi,lo}, layout [px][ci] bf16, 16B-chunk XOR swizzle.
#define RPC 32
#define NPX 128
#define A_PLANE (9 * 32 * 128)
#define OFF_B   (2 * A_PLANE)              // 73728
#define B_PLANE (132 * 128)                // 16896 per (split, slot)
#define HMMA_SMEM (OFF_B + 8 * B_PLANE)    // 208896

template <int COUT, int NSLICE, bool RELU, bool PACK_OUT>
__global__ __launch_bounds__(256, 1)
void conv3x3_hmma(const uint32_t* __restrict__ in, const float* __restrict__ wgt,
                  const float* __restrict__ bias, void* __restrict__ outv) {
    extern __shared__ __align__(128) char smem[];
    const uint32_t sb = smem_u32(smem);
    const int tid = threadIdx.x, warp = tid >> 5, lane = tid & 31;
    const int x0 = blockIdx.x * NPX;
    const int y0 = blockIdx.y * RPC;
    const int mslice = blockIdx.z % NSLICE;
    const int b = blockIdx.z / NSLICE;
    const int co_base = mslice * 32;

    // ---- stage A: 9 taps x 32 co x 64 ci, hi+lo, swizzled [co][ci] ----
    {
        const int cpl = lane & 3, po = lane >> 2;
        for (int it = warp; it < 288; it += 8) {
            int t = it / 32, r = it & 31;
            int cotile = r >> 3, c = r & 7;
            int co = cotile * 8 + po;
            int ci0 = c * 8 + cpl * 2;
            int cog = co_base + co;
            float f0 = 0.f, f1 = 0.f;
            if (cog < COUT) {
                const float* wp = wgt + ((size_t)cog * 64 + ci0) * 9 + t;
                f0 = __ldg(wp);
                f1 = __ldg(wp + 9);
            }
            uint32_t hi, lo;
            split2(f0, f1, hi, lo);
            uint32_t off = (uint32_t)((t * 32 + co) * 128 +
                                      ((c ^ (co & 7)) << 4) + cpl * 4);
            asm volatile("st.shared.b32 [%0], %1;" :: "r"(sb + off), "r"(hi) : "memory");
            asm volatile("st.shared.b32 [%0], %1;" :: "r"(sb + A_PLANE + off), "r"(lo) : "memory");
        }
    }

    // ---- B row-plane stage: plane row yy -> slot (yy+4)&3 ----
    auto stage_B = [&](int yy) {
        const int slot = (yy + 4) & 3;
        const bool ok_row = (yy >= 0) && (yy < HH);
        const uint32_t* src = in + ((size_t)b * 64 * HH + (ok_row ? yy : 0)) * WW;
        const int cpl = lane & 3, po = lane >> 2;
        const uint32_t bH = sb + OFF_B + slot * B_PLANE;
        const uint32_t bL = sb + OFF_B + (4 + slot) * B_PLANE;
        for (int it = warp; it < 136; it += 8) {
            int c = it & 7, pxt = it >> 3;
            int px = pxt * 8 + po;
            if (px >= 132) continue;
            int ci0 = c * 8 + cpl * 2;
            int gx = x0 - 1 + px;
            bool ok = ok_row && (gx >= 0) && (gx < WW);
            const uint32_t* p = src + (size_t)ci0 * HWSZ + (ok ? gx : 0);
            uint32_t u0 = ok ? __ldg(p) : 0u;
            uint32_t u1 = ok ? __ldg(p + HWSZ) : 0u;
            uint32_t hi, lo;
            asm("prmt.b32 %0, %1, %2, 0x5410;" : "=r"(hi) : "r"(u0), "r"(u1));
            asm("prmt.b32 %0, %1, %2, 0x7632;" : "=r"(lo) : "r"(u0), "r"(u1));
            uint32_t off = (uint32_t)(px * 128 + ((c ^ (px & 7)) << 4) + cpl * 4);
            asm volatile("st.shared.b32 [%0], %1;" :: "r"(bH + off), "r"(hi) : "memory");
            asm volatile("st.shared.b32 [%0], %1;" :: "r"(bL + off), "r"(lo) : "memory");
        }
    };

    stage_B(y0 - 1);
    stage_B(y0);
    stage_B(y0 + 1);
    stage_B(y0 + 2);
    __syncthreads();

    const int r7 = lane & 7, g = lane >> 3;
    const int a_row = r7 + ((g & 1) << 3);
    const int a_kh = g >> 1;
    const int b_noff = r7 + ((g >> 1) << 3);
    const int b_kh = g & 1;
    const int nb = warp * 16;
    const int row_d = lane >> 2, col_d = (lane & 3) * 2;

    const int yend = y0 + RPC;
#pragma unroll 1
    for (int y = y0; y < yend; y += 2) {
        float acc[2][4][4];
#pragma unroll
        for (int r = 0; r < 2; r++)
#pragma unroll
            for (int i = 0; i < 4; i++)
#pragma unroll
                for (int j = 0; j < 4; j++) acc[r][i][j] = 0.f;

        int sl[4];
#pragma unroll
        for (int i = 0; i < 4; i++) sl[i] = (y - 1 + i + 4) & 3;

#pragma unroll 1
        for (int t = 0; t < 9; t++) {
            const int dy = t / 3, dx = t % 3;
            const uint32_t aH = sb + (uint32_t)(t * 32 * 128);
            const uint32_t aL = aH + A_PLANE;
            const uint32_t b0H = sb + OFF_B + sl[dy] * B_PLANE;       // row y
            const uint32_t b0L = b0H + 4 * B_PLANE;
            const uint32_t b1H = sb + OFF_B + sl[dy + 1] * B_PLANE;   // row y+1
            const uint32_t b1L = b1H + 4 * B_PLANE;
            const int pxm = nb + dx + b_noff;
            const uint32_t bRow = (uint32_t)(pxm * 128);
            const int bx7 = pxm & 7;
#pragma unroll
            for (int kc = 0; kc < 4; kc++) {
                const uint32_t cA = (uint32_t)((((kc << 1) | a_kh) ^ r7) << 4);
                const uint32_t cB = (uint32_t)((((kc << 1) | b_kh) ^ bx7) << 4);
                uint32_t AH[2][4], AL[2][4];
                uint32_t BH0[4], BL0[4], BH1[4], BL1[4];
                ldmx4(AH[0][0], AH[0][1], AH[0][2], AH[0][3],
                      aH + (uint32_t)(a_row * 128) + cA);
                ldmx4(AH[1][0], AH[1][1], AH[1][2], AH[1][3],
                      aH + (uint32_t)((a_row + 16) * 128) + cA);
                ldmx4(AL[0][0], AL[0][1], AL[0][2], AL[0][3],
                      aL + (uint32_t)(a_row * 128) + cA);
                ldmx4(AL[1][0], AL[1][1], AL[1][2], AL[1][3],
                      aL + (uint32_t)((a_row + 16) * 128) + cA);
                ldmx4(BH0[0], BH0[1], BH0[2], BH0[3], b0H + bRow + cB);
                ldmx4(BL0[0], BL0[1], BL0[2], BL0[3], b0L + bRow + cB);
                ldmx4(BH1[0], BH1[1], BH1[2], BH1[3], b1H + bRow + cB);
                ldmx4(BL1[0], BL1[1], BL1[2], BL1[3], b1L + bRow + cB);
#pragma unroll
                for (int mt = 0; mt < 2; mt++) {
#pragma unroll
                    for (int nt = 0; nt < 2; nt++) {
                        float* c0 = acc[0][mt * 2 + nt];
                        mma16816(c0, AH[mt], BH0[nt * 2], BH0[nt * 2 + 1]);
                        mma16816(c0, AH[mt], BL0[nt * 2], BL0[nt * 2 + 1]);
                        mma16816(c0, AL[mt], BH0[nt * 2], BH0[nt * 2 + 1]);
                        float* c1 = acc[1][mt * 2 + nt];
                        mma16816(c1, AH[mt], BH1[nt * 2], BH1[nt * 2 + 1]);
                        mma16816(c1, AH[mt], BL1[nt * 2], BL1[nt * 2 + 1]);
                        mma16816(c1, AL[mt], BH1[nt * 2], BH1[nt * 2 + 1]);
                    }
                }
            }
        }

        // epilogue (global only, no SMEM)
#pragma unroll
        for (int r = 0; r < 2; r++) {
            const int yy = y + r;
#pragma unroll
            for (int mt = 0; mt < 2; mt++) {
#pragma unroll
                for (int nt = 0; nt < 2; nt++) {
                    float* c = acc[r][mt * 2 + nt];
                    int x = x0 + nb + nt * 8 + col_d;
#pragma unroll
                    for (int h = 0; h < 2; h++) {
                        int co = co_base + mt * 16 + row_d + h * 8;
                        if (co < COUT) {
                            float bv = __ldg(bias + co);
                            float v0 = c[2 * h] + bv, v1 = c[2 * h + 1] + bv;
                            if (RELU) { v0 = fmaxf(v0, 0.f); v1 = fmaxf(v1, 0.f); }
                            size_t idx = (((size_t)b * COUT + co) * HH + yy) * WW + x;
                            if (PACK_OUT) {
                                uint2 u = make_uint2(pack_split(v0), pack_split(v1));
                                *reinterpret_cast<uint2*>((uint32_t*)outv + idx) = u;
                            } else {
                                *reinterpret_cast<float2*>((float*)outv + idx) =
                                    make_float2(v0, v1);
                            }
                        }
                    }
                }
            }
        }

        if (y + 2 < yend) {
            __syncthreads();
            stage_B(y + 3);
            stage_B(y + 4);
            __syncthreads();
        }
    }
}

// ======================= scalar conv1 (4 -> 64) =============================
__device__ __forceinline__ unsigned long long pack2(float x, float y) {
    unsigned long long r;
    asm("mov.b64 %0, {%1, %2};" : "=l"(r) : "f"(x), "f"(y));
    return r;
}
__device__ __forceinline__ unsigned long long bcast2(float x) { return pack2(x, x); }
__device__ __forceinline__ float2 unpack2(unsigned long long v) {
    float2 f;
    asm("mov.b64 {%0, %1}, %2;" : "=f"(f.x), "=f"(f.y) : "l"(v));
    return f;
}
__device__ __forceinline__ unsigned long long ffma2(unsigned long long a,
                                                    unsigned long long b,
                                                    unsigned long long c) {
    unsigned long long d;
    asm("fma.rn.f32x2 %0, %1, %2, %3;" : "=l"(d) : "l"(a), "l"(b), "l"(c));
    return d;
}

__global__ __launch_bounds__(512, 1)
void conv1_kernel(const float* __restrict__ rgb, const float* __restrict__ depth,
                  const float* __restrict__ wgt, const float* __restrict__ bias,
                  uint32_t* __restrict__ out) {
    constexpr int QS = 16, PIX = 4, CCH = 4;
    constexpr int NP = 8, NP2 = 4;
    __shared__ __align__(16) float ws[CCH][9][4][QS];

    const int tid = threadIdx.x;
    const int lx = tid & 31;
    const int ty = (tid >> 5) & 3;
    const int q = tid >> 7;
    const int x = blockIdx.x * 32 + lx;
    const int y0 = blockIdx.y * (4 * PIX) + ty * PIX;
    const int b = blockIdx.z;
    const int co0 = q * QS;

    unsigned long long acc[PIX][NP];
#pragma unroll
    for (int pr = 0; pr < NP; pr++) {
        unsigned long long bb = pack2(__ldg(bias + co0 + 2 * pr),
                                      __ldg(bias + co0 + 2 * pr + 1));
#pragma unroll
        for (int p = 0; p < PIX; p++) acc[p][pr] = bb;
    }

    int rowoff[PIX + 2];
    bool rok[PIX + 2];
#pragma unroll
    for (int r = 0; r < PIX + 2; r++) {
        int yy = y0 - 1 + r;
        rok[r] = (yy >= 0) && (yy < HH);
        rowoff[r] = yy * WW;
    }
    const bool xok0 = (x > 0), xok2 = (x < WW - 1);

    for (int i = tid; i < CCH * 9 * 4 * QS; i += 512) {
        int col = i % QS;
        int qq = (i / QS) % 4;
        int t = (i / (QS * 4)) % 9;
        int cl = i / (QS * 4 * 9);
        (&ws[0][0][0][0])[i] = __ldg(wgt + ((size_t)(qq * QS + col) * 4 + cl) * 9 + t);
    }
    __syncthreads();

#pragma unroll
    for (int ci = 0; ci < 4; ci++) {
        const float* ip = (ci < 3) ? (rgb + ((size_t)b * 3 + ci) * HWSZ)
                                   : (depth + (size_t)b * HWSZ);
        const float* ipx = ip + x;
        float v[PIX + 2][3];
#pragma unroll
        for (int r = 0; r < PIX + 2; r++) {
            v[r][0] = (rok[r] && xok0) ? __ldg(ipx + rowoff[r] - 1) : 0.f;
            v[r][1] = rok[r] ? __ldg(ipx + rowoff[r]) : 0.f;
            v[r][2] = (rok[r] && xok2) ? __ldg(ipx + rowoff[r] + 1) : 0.f;
        }
#pragma unroll
        for (int dy = 0; dy < 3; dy++) {
#pragma unroll
            for (int dx = 0; dx < 3; dx++) {
                const ulonglong2* wp =
                    reinterpret_cast<const ulonglong2*>(&ws[ci][dy * 3 + dx][q][0]);
                ulonglong2 wq[NP2];
#pragma unroll
                for (int j = 0; j < NP2; j++) wq[j] = wp[j];
#pragma unroll
                for (int p = 0; p < PIX; p++) {
                    unsigned long long vv = bcast2(v[p + dy][dx]);
#pragma unroll
                    for (int j = 0; j < NP2; j++) {
                        acc[p][2 * j] = ffma2(vv, wq[j].x, acc[p][2 * j]);
                        acc[p][2 * j + 1] = ffma2(vv, wq[j].y, acc[p][2 * j + 1]);
                    }
                }
            }
        }
    }

#pragma unroll
    for (int p = 0; p < PIX; p++) {
        size_t base = ((size_t)b * 64) * HWSZ + (size_t)(y0 + p) * WW + x;
#pragma unroll
        for (int pr = 0; pr < NP; pr++) {
            float2 f = unpack2(acc[p][pr]);
            f.x = fmaxf(f.x, 0.f);
            f.y = fmaxf(f.y, 0.f);
            int co = co0 + 2 * pr;
            out[base + (size_t)co * HWSZ] = pack_split(f.x);
            out[base + (size_t)(co + 1) * HWSZ] = pack_split(f.y);
        }
    }
}

// ======================= softmax + bokeh ====================================
__global__ __launch_bounds__(128, 4)
void softmax_bokeh_kernel(const float* __restrict__ logits,
                          const float* __restrict__ rgb,
                          float* __restrict__ out) {
    __shared__ float tile[3][12][40];
    const int tid = threadIdx.x;
    const int lx = tid & 31;
    const int ty = tid >> 5;
    const int x = blockIdx.x * 32 + lx;
    const int y = blockIdx.y * 4 + ty;
    const int b = blockIdx.z;
    const int gx0 = blockIdx.x * 32 - 4;
    const int gy0 = blockIdx.y * 4 - 4;

    for (int i = tid; i < 3 * 12 * 40; i += 128) {
        int xx = i % 40;
        int yy = (i / 40) % 12;
        int c = i / 480;
        int gx = gx0 + xx, gy = gy0 + yy;
        float v = 0.f;
        if (gx >= 0 && gx < WW && gy >= 0 && gy < HH)
            v = rgb[((size_t)b * 3 + c) * HWSZ + (size_t)gy * WW + gx];
        tile[c][yy][xx] = v;
    }
    __syncthreads();

    float lg[81];
    const float* lp = logits + (size_t)b * 81 * HWSZ + (size_t)y * WW + x;
    float m = -1e30f;
#pragma unroll
    for (int t = 0; t < 81; t++) {
        lg[t] = __ldg(lp + (size_t)t * HWSZ);
        m = fmaxf(m, lg[t]);
    }
    float s = 0.f;
#pragma unroll
    for (int t = 0; t < 81; t++) {
        float e = __expf(lg[t] - m);
        lg[t] = e;
        s += e;
    }
    float inv = 1.f / s;

    float r = 0.f, g = 0.f, bl = 0.f;
#pragma unroll
    for (int dy = 0; dy < 9; dy++) {
#pragma unroll
        for (int dx = 0; dx < 9; dx++) {
            float f = lg[dy * 9 + dx] * inv;
            r += f * tile[0][ty + dy][lx + dx];
            g += f * tile[1][ty + dy][lx + dx];
            bl += f * tile[2][ty + dy][lx + dx];
        }
    }
    size_t ob = (size_t)b * 3 * HWSZ + (size_t)y * WW + x;
    out[ob] = r;
    out[ob + HWSZ] = g;
    out[ob + 2 * HWSZ] = bl;
}

// ======================= launch =============================================
extern "C" void kernel_launch(void* const* d_in, const int* in_sizes, int n_in,
                              void* d_out, int out_size) {
    const float* rgb   = (const float*)d_in[0];
    const float* depth = (const float*)d_in[1];
    const float* w1    = (const float*)d_in[2];
    const float* b1    = (const float*)d_in[3];
    const float* w2    = (const float*)d_in[4];
    const float* b2    = (const float*)d_in[5];
    const float* w3    = (const float*)d_in[6];
    const float* b3    = (const float*)d_in[7];
    float* out = (float*)d_out;

    uint32_t *h1, *h2;
    float* lg;
    cudaGetSymbolAddress((void**)&h1, g_h1);
    cudaGetSymbolAddress((void**)&h2, g_h2);
    cudaGetSymbolAddress((void**)&lg, g_logits);

    cudaFuncSetAttribute(conv3x3_hmma<64, 2, true, true>,
                         cudaFuncAttributeMaxDynamicSharedMemorySize, HMMA_SMEM);
    cudaFuncSetAttribute(conv3x3_hmma<81, 3, false, false>,
                         cudaFuncAttributeMaxDynamicSharedMemorySize, HMMA_SMEM);

    // conv1: scalar FFMA2, writes split-format h1
    conv1_kernel<<<dim3(WW / 32, HH / 16, BATCH), 512>>>(rgb, depth, w1, b1, h1);
    // conv2: HMMA implicit GEMM (2 co-slices of 32), split in / split out
    conv3x3_hmma<64, 2, true, true><<<dim3(WW / NPX, HH / RPC, 2 * BATCH), 256,
                                      HMMA_SMEM>>>(h1, w2, b2, h2);
    // conv3: HMMA implicit GEMM (3 co-slices of 32, 81 real), split in / f32 out
    conv3x3_hmma<81, 3, false, false><<<dim3(WW / NPX, HH / RPC, 3 * BATCH), 256,
                                        HMMA_SMEM>>>(h2, w3, b3, lg);
    // softmax + bokeh
    softmax_bokeh_kernel<<<dim3(WW / 32, HH / 4, BATCH), 128>>>(lg, rgb, out);
}

// round 8
// speedup vs baseline: 1.7181x; 1.0245x over previous
#include <cuda_runtime.h>
#include <cuda_bf16.h>
#include <cstdint>
#include <cstddef>

#define HH 384
#define WW 384
#define BATCH 4
#define HWSZ (HH * WW)

// h1/h2 in split format: u32 = bf16(hi) | bf16(lo)<<16
__device__ uint32_t g_h1[(size_t)BATCH * 64 * HWSZ];
__device__ uint32_t g_h2[(size_t)BATCH * 64 * HWSZ];
__device__ float    g_logits[(size_t)BATCH * 81 * HWSZ];

// =============================== helpers ====================================
__device__ __forceinline__ uint32_t smem_u32(const void* p) {
    uint32_t a;
    asm("{ .reg .u64 t; cvta.to.shared.u64 t, %1; cvt.u32.u64 %0, t; }"
        : "=r"(a) : "l"(p));
    return a;
}
__device__ __forceinline__ void ldmx4(uint32_t& r0, uint32_t& r1, uint32_t& r2,
                                      uint32_t& r3, uint32_t addr) {
    asm volatile("ldmatrix.sync.aligned.m8n8.x4.shared.b16 {%0,%1,%2,%3}, [%4];"
                 : "=r"(r0), "=r"(r1), "=r"(r2), "=r"(r3) : "r"(addr));
}
__device__ __forceinline__ void mma16816(float* c, const uint32_t* a,
                                         uint32_t b0, uint32_t b1) {
    asm volatile(
        "mma.sync.aligned.m16n8k16.row.col.f32.bf16.bf16.f32 "
        "{%0,%1,%2,%3}, {%4,%5,%6,%7}, {%8,%9}, {%0,%1,%2,%3};"
        : "+f"(c[0]), "+f"(c[1]), "+f"(c[2]), "+f"(c[3])
        : "r"(a[0]), "r"(a[1]), "r"(a[2]), "r"(a[3]), "r"(b0), "r"(b1));
}
// pack two f32 -> bf16x2 (low half = f0), plus residual word
__device__ __forceinline__ void split2(float f0, float f1, uint32_t& hi,
                                       uint32_t& lo) {
    asm("cvt.rn.bf16x2.f32 %0, %1, %2;" : "=r"(hi) : "f"(f1), "f"(f0));
    float f0h = __uint_as_float(hi << 16);
    float f1h = __uint_as_float(hi & 0xFFFF0000u);
    asm("cvt.rn.bf16x2.f32 %0, %1, %2;" : "=r"(lo) : "f"(f1 - f1h), "f"(f0 - f0h));
}
// scalar split pack: u32 = bf16(v) | bf16(v - hi)<<16
__device__ __forceinline__ uint32_t pack_split(float v) {
    uint32_t h;
    asm("cvt.rn.bf16x2.f32 %0, %1, %1;" : "=r"(h) : "f"(v));
    float hf = __uint_as_float(h << 16);
    float l = v - hf;
    uint32_t lb;
    asm("cvt.rn.bf16x2.f32 %0, %1, %1;" : "=r"(lb) : "f"(l));
    return (h & 0xFFFFu) | (lb << 16);
}

// ===================== HMMA implicit-GEMM 3x3 conv ==========================
// Per CTA: co-slice M=32, px-tile N=128, persist over RPC=32 rows (2 per iter).
// A (weights, 9 taps, hi+lo) staged once; B (split-format input) ring of 4
// row-planes x {hi,lo}, layout [px][ci] bf16, 16B-chunk XOR swizzle.
// Mainloop nest (kc -> dx -> planes -> dy) shares each B fragment between the
// two output rows (tap dy for row y == tap dy-1 for row y+1).
#define RPC 32
#define NPX 128
#define A_PLANE (9 * 32 * 128)
#define OFF_B   (2 * A_PLANE)              // 73728
#define B_PLANE (132 * 128)                // 16896 per (split, slot)
#define HMMA_SMEM (OFF_B + 8 * B_PLANE)    // 208896

template <int COUT, int NSLICE, bool RELU, bool PACK_OUT>
__global__ __launch_bounds__(256, 1)
void conv3x3_hmma(const uint32_t* __restrict__ in, const float* __restrict__ wgt,
                  const float* __restrict__ bias, void* __restrict__ outv) {
    extern __shared__ __align__(128) char smem[];
    const uint32_t sb = smem_u32(smem);
    const int tid = threadIdx.x, warp = tid >> 5, lane = tid & 31;
    const int x0 = blockIdx.x * NPX;
    const int y0 = blockIdx.y * RPC;
    const int mslice = blockIdx.z % NSLICE;
    const int b = blockIdx.z / NSLICE;
    const int co_base = mslice * 32;

    // ---- stage A: 9 taps x 32 co x 64 ci, hi+lo, swizzled [co][ci] ----
    {
        const int cpl = lane & 3, po = lane >> 2;
        for (int it = warp; it < 288; it += 8) {
            int t = it / 32, r = it & 31;
            int cotile = r >> 3, c = r & 7;
            int co = cotile * 8 + po;
            int ci0 = c * 8 + cpl * 2;
            int cog = co_base + co;
            float f0 = 0.f, f1 = 0.f;
            if (cog < COUT) {
                const float* wp = wgt + ((size_t)cog * 64 + ci0) * 9 + t;
                f0 = __ldg(wp);
                f1 = __ldg(wp + 9);
            }
            uint32_t hi, lo;
            split2(f0, f1, hi, lo);
            uint32_t off = (uint32_t)((t * 32 + co) * 128 +
                                      ((c ^ (co & 7)) << 4) + cpl * 4);
            asm volatile("st.shared.b32 [%0], %1;" :: "r"(sb + off), "r"(hi) : "memory");
            asm volatile("st.shared.b32 [%0], %1;" :: "r"(sb + A_PLANE + off), "r"(lo) : "memory");
        }
    }

    // ---- B row-plane stage: plane row yy -> slot (yy+4)&3 ----
    auto stage_B = [&](int yy) {
        const int slot = (yy + 4) & 3;
        const bool ok_row = (yy >= 0) && (yy < HH);
        const uint32_t* src = in + ((size_t)b * 64 * HH + (ok_row ? yy : 0)) * WW;
        const int cpl = lane & 3, po = lane >> 2;
        const uint32_t bH = sb + OFF_B + slot * B_PLANE;
        const uint32_t bL = sb + OFF_B + (4 + slot) * B_PLANE;
        for (int it = warp; it < 136; it += 8) {
            int c = it & 7, pxt = it >> 3;
            int px = pxt * 8 + po;
            if (px >= 132) continue;
            int ci0 = c * 8 + cpl * 2;
            int gx = x0 - 1 + px;
            bool ok = ok_row && (gx >= 0) && (gx < WW);
            const uint32_t* p = src + (size_t)ci0 * HWSZ + (ok ? gx : 0);
            uint32_t u0 = ok ? __ldg(p) : 0u;
            uint32_t u1 = ok ? __ldg(p + HWSZ) : 0u;
            uint32_t hi, lo;
            asm("prmt.b32 %0, %1, %2, 0x5410;" : "=r"(hi) : "r"(u0), "r"(u1));
            asm("prmt.b32 %0, %1, %2, 0x7632;" : "=r"(lo) : "r"(u0), "r"(u1));
            uint32_t off = (uint32_t)(px * 128 + ((c ^ (px & 7)) << 4) + cpl * 4);
            asm volatile("st.shared.b32 [%0], %1;" :: "r"(bH + off), "r"(hi) : "memory");
            asm volatile("st.shared.b32 [%0], %1;" :: "r"(bL + off), "r"(lo) : "memory");
        }
    };

    stage_B(y0 - 1);
    stage_B(y0);
    stage_B(y0 + 1);
    stage_B(y0 + 2);
    __syncthreads();

    const int r7 = lane & 7, g = lane >> 3;
    const int a_row = r7 + ((g & 1) << 3);
    const int a_kh = g >> 1;
    const int b_noff = r7 + ((g >> 1) << 3);
    const int b_kh = g & 1;
    const int nb = warp * 16;
    const int row_d = lane >> 2, col_d = (lane & 3) * 2;

    const int yend = y0 + RPC;
#pragma unroll 1
    for (int y = y0; y < yend; y += 2) {
        float acc[2][4][4];
#pragma unroll
        for (int r = 0; r < 2; r++)
#pragma unroll
            for (int i = 0; i < 4; i++)
#pragma unroll
                for (int j = 0; j < 4; j++) acc[r][i][j] = 0.f;

        // plane slots: sl[i] = slot of input row (y-1+i), i=0..3
        uint32_t plH[4], plL[4];
#pragma unroll
        for (int i = 0; i < 4; i++) {
            int slot = (y - 1 + i + 4) & 3;
            plH[i] = sb + OFF_B + slot * B_PLANE;
            plL[i] = plH[i] + 4 * B_PLANE;
        }

#pragma unroll
        for (int kc = 0; kc < 4; kc++) {
#pragma unroll
            for (int dx = 0; dx < 3; dx++) {
                const int pxm = nb + dx + b_noff;
                const uint32_t bRow = (uint32_t)(pxm * 128);
                const uint32_t cB =
                    (uint32_t)((((kc << 1) | b_kh) ^ (pxm & 7)) << 4);
                // load B fragments for all 4 planes, hi+lo (8 LDSM.x4)
                uint32_t BF[4][2][4];
#pragma unroll
                for (int pl = 0; pl < 4; pl++) {
                    ldmx4(BF[pl][0][0], BF[pl][0][1], BF[pl][0][2], BF[pl][0][3],
                          plH[pl] + bRow + cB);
                    ldmx4(BF[pl][1][0], BF[pl][1][1], BF[pl][1][2], BF[pl][1][3],
                          plL[pl] + bRow + cB);
                }
                const uint32_t cA = (uint32_t)((((kc << 1) | a_kh) ^ r7) << 4);
#pragma unroll
                for (int dy = 0; dy < 3; dy++) {
                    const int t = dy * 3 + dx;
                    const uint32_t aH = sb + (uint32_t)(t * 32 * 128);
                    const uint32_t aL = aH + A_PLANE;
                    uint32_t AH[2][4], AL[2][4];
                    ldmx4(AH[0][0], AH[0][1], AH[0][2], AH[0][3],
                          aH + (uint32_t)(a_row * 128) + cA);
                    ldmx4(AH[1][0], AH[1][1], AH[1][2], AH[1][3],
                          aH + (uint32_t)((a_row + 16) * 128) + cA);
                    ldmx4(AL[0][0], AL[0][1], AL[0][2], AL[0][3],
                          aL + (uint32_t)(a_row * 128) + cA);
                    ldmx4(AL[1][0], AL[1][1], AL[1][2], AL[1][3],
                          aL + (uint32_t)((a_row + 16) * 128) + cA);
                    // row 0 (y): plane dy; row 1 (y+1): plane dy+1
#pragma unroll
                    for (int mt = 0; mt < 2; mt++) {
#pragma unroll
                        for (int nt = 0; nt < 2; nt++) {
                            float* c0 = acc[0][mt * 2 + nt];
                            mma16816(c0, AH[mt], BF[dy][0][nt * 2], BF[dy][0][nt * 2 + 1]);
                            mma16816(c0, AH[mt], BF[dy][1][nt * 2], BF[dy][1][nt * 2 + 1]);
                            mma16816(c0, AL[mt], BF[dy][0][nt * 2], BF[dy][0][nt * 2 + 1]);
                            float* c1 = acc[1][mt * 2 + nt];
                            mma16816(c1, AH[mt], BF[dy + 1][0][nt * 2], BF[dy + 1][0][nt * 2 + 1]);
                            mma16816(c1, AH[mt], BF[dy + 1][1][nt * 2], BF[dy + 1][1][nt * 2 + 1]);
                            mma16816(c1, AL[mt], BF[dy + 1][0][nt * 2], BF[dy + 1][0][nt * 2 + 1]);
                        }
                    }
                }
            }
        }

        // epilogue (global only, no SMEM)
#pragma unroll
        for (int r = 0; r < 2; r++) {
            const int yy = y + r;
#pragma unroll
            for (int mt = 0; mt < 2; mt++) {
#pragma unroll
                for (int nt = 0; nt < 2; nt++) {
                    float* c = acc[r][mt * 2 + nt];
                    int x = x0 + nb + nt * 8 + col_d;
#pragma unroll
                    for (int h = 0; h < 2; h++) {
                        int co = co_base + mt * 16 + row_d + h * 8;
                        if (co < COUT) {
                            float bv = __ldg(bias + co);
                            float v0 = c[2 * h] + bv, v1 = c[2 * h + 1] + bv;
                            if (RELU) { v0 = fmaxf(v0, 0.f); v1 = fmaxf(v1, 0.f); }
                            size_t idx = (((size_t)b * COUT + co) * HH + yy) * WW + x;
                            if (PACK_OUT) {
                                uint2 u = make_uint2(pack_split(v0), pack_split(v1));
                                *reinterpret_cast<uint2*>((uint32_t*)outv + idx) = u;
                            } else {
                                *reinterpret_cast<float2*>((float*)outv + idx) =
                                    make_float2(v0, v1);
                            }
                        }
                    }
                }
            }
        }

        if (y + 2 < yend) {
            __syncthreads();
            stage_B(y + 3);
            stage_B(y + 4);
            __syncthreads();
        }
    }
}

// ======================= scalar conv1 (4 -> 64) =============================
__device__ __forceinline__ unsigned long long pack2(float x, float y) {
    unsigned long long r;
    asm("mov.b64 %0, {%1, %2};" : "=l"(r) : "f"(x), "f"(y));
    return r;
}
__device__ __forceinline__ unsigned long long bcast2(float x) { return pack2(x, x); }
__device__ __forceinline__ float2 unpack2(unsigned long long v) {
    float2 f;
    asm("mov.b64 {%0, %1}, %2;" : "=f"(f.x), "=f"(f.y) : "l"(v));
    return f;
}
__device__ __forceinline__ unsigned long long ffma2(unsigned long long a,
                                                    unsigned long long b,
                                                    unsigned long long c) {
    unsigned long long d;
    asm("fma.rn.f32x2 %0, %1, %2, %3;" : "=l"(d) : "l"(a), "l"(b), "l"(c));
    return d;
}

__global__ __launch_bounds__(512, 1)
void conv1_kernel(const float* __restrict__ rgb, const float* __restrict__ depth,
                  const float* __restrict__ wgt, const float* __restrict__ bias,
                  uint32_t* __restrict__ out) {
    constexpr int QS = 16, PIX = 4, CCH = 4;
    constexpr int NP = 8, NP2 = 4;
    __shared__ __align__(16) float ws[CCH][9][4][QS];

    const int tid = threadIdx.x;
    const int lx = tid & 31;
    const int ty = (tid >> 5) & 3;
    const int q = tid >> 7;
    const int x = blockIdx.x * 32 + lx;
    const int y0 = blockIdx.y * (4 * PIX) + ty * PIX;
    const int b = blockIdx.z;
    const int co0 = q * QS;

    unsigned long long acc[PIX][NP];
#pragma unroll
    for (int pr = 0; pr < NP; pr++) {
        unsigned long long bb = pack2(__ldg(bias + co0 + 2 * pr),
                                      __ldg(bias + co0 + 2 * pr + 1));
#pragma unroll
        for (int p = 0; p < PIX; p++) acc[p][pr] = bb;
    }

    int rowoff[PIX + 2];
    bool rok[PIX + 2];
#pragma unroll
    for (int r = 0; r < PIX + 2; r++) {
        int yy = y0 - 1 + r;
        rok[r] = (yy >= 0) && (yy < HH);
        rowoff[r] = yy * WW;
    }
    const bool xok0 = (x > 0), xok2 = (x < WW - 1);

    for (int i = tid; i < CCH * 9 * 4 * QS; i += 512) {
        int col = i % QS;
        int qq = (i / QS) % 4;
        int t = (i / (QS * 4)) % 9;
        int cl = i / (QS * 4 * 9);
        (&ws[0][0][0][0])[i] = __ldg(wgt + ((size_t)(qq * QS + col) * 4 + cl) * 9 + t);
    }
    __syncthreads();

#pragma unroll
    for (int ci = 0; ci < 4; ci++) {
        const float* ip = (ci < 3) ? (rgb + ((size_t)b * 3 + ci) * HWSZ)
                                   : (depth + (size_t)b * HWSZ);
        const float* ipx = ip + x;
        float v[PIX + 2][3];
#pragma unroll
        for (int r = 0; r < PIX + 2; r++) {
            v[r][0] = (rok[r] && xok0) ? __ldg(ipx + rowoff[r] - 1) : 0.f;
            v[r][1] = rok[r] ? __ldg(ipx + rowoff[r]) : 0.f;
            v[r][2] = (rok[r] && xok2) ? __ldg(ipx + rowoff[r] + 1) : 0.f;
        }
#pragma unroll
        for (int dy = 0; dy < 3; dy++) {
#pragma unroll
            for (int dx = 0; dx < 3; dx++) {
                const ulonglong2* wp =
                    reinterpret_cast<const ulonglong2*>(&ws[ci][dy * 3 + dx][q][0]);
                ulonglong2 wq[NP2];
#pragma unroll
                for (int j = 0; j < NP2; j++) wq[j] = wp[j];
#pragma unroll
                for (int p = 0; p < PIX; p++) {
                    unsigned long long vv = bcast2(v[p + dy][dx]);
#pragma unroll
                    for (int j = 0; j < NP2; j++) {
                        acc[p][2 * j] = ffma2(vv, wq[j].x, acc[p][2 * j]);
                        acc[p][2 * j + 1] = ffma2(vv, wq[j].y, acc[p][2 * j + 1]);
                    }
                }
            }
        }
    }

#pragma unroll
    for (int p = 0; p < PIX; p++) {
        size_t base = ((size_t)b * 64) * HWSZ + (size_t)(y0 + p) * WW + x;
#pragma unroll
        for (int pr = 0; pr < NP; pr++) {
            float2 f = unpack2(acc[p][pr]);
            f.x = fmaxf(f.x, 0.f);
            f.y = fmaxf(f.y, 0.f);
            int co = co0 + 2 * pr;
            out[base + (size_t)co * HWSZ] = pack_split(f.x);
            out[base + (size_t)(co + 1) * HWSZ] = pack_split(f.y);
        }
    }
}

// ======================= softmax + bokeh ====================================
__global__ __launch_bounds__(128, 4)
void softmax_bokeh_kernel(const float* __restrict__ logits,
                          const float* __restrict__ rgb,
                          float* __restrict__ out) {
    __shared__ float tile[3][12][40];
    const int tid = threadIdx.x;
    const int lx = tid & 31;
    const int ty = tid >> 5;
    const int x = blockIdx.x * 32 + lx;
    const int y = blockIdx.y * 4 + ty;
    const int b = blockIdx.z;
    const int gx0 = blockIdx.x * 32 - 4;
    const int gy0 = blockIdx.y * 4 - 4;

    for (int i = tid; i < 3 * 12 * 40; i += 128) {
        int xx = i % 40;
        int yy = (i / 40) % 12;
        int c = i / 480;
        int gx = gx0 + xx, gy = gy0 + yy;
        float v = 0.f;
        if (gx >= 0 && gx < WW && gy >= 0 && gy < HH)
            v = rgb[((size_t)b * 3 + c) * HWSZ + (size_t)gy * WW + gx];
        tile[c][yy][xx] = v;
    }
    __syncthreads();

    float lg[81];
    const float* lp = logits + (size_t)b * 81 * HWSZ + (size_t)y * WW + x;
    float m = -1e30f;
#pragma unroll
    for (int t = 0; t < 81; t++) {
        lg[t] = __ldg(lp + (size_t)t * HWSZ);
        m = fmaxf(m, lg[t]);
    }
    float s = 0.f;
#pragma unroll
    for (int t = 0; t < 81; t++) {
        float e = __expf(lg[t] - m);
        lg[t] = e;
        s += e;
    }
    float inv = 1.f / s;

    float r = 0.f, g = 0.f, bl = 0.f;
#pragma unroll
    for (int dy = 0; dy < 9; dy++) {
#pragma unroll
        for (int dx = 0; dx < 9; dx++) {
            float f = lg[dy * 9 + dx] * inv;
            r += f * tile[0][ty + dy][lx + dx];
            g += f * tile[1][ty + dy][lx + dx];
            bl += f * tile[2][ty + dy][lx + dx];
        }
    }
    size_t ob = (size_t)b * 3 * HWSZ + (size_t)y * WW + x;
    out[ob] = r;
    out[ob + HWSZ] = g;
    out[ob + 2 * HWSZ] = bl;
}

// ======================= launch =============================================
extern "C" void kernel_launch(void* const* d_in, const int* in_sizes, int n_in,
                              void* d_out, int out_size) {
    const float* rgb   = (const float*)d_in[0];
    const float* depth = (const float*)d_in[1];
    const float* w1    = (const float*)d_in[2];
    const float* b1    = (const float*)d_in[3];
    const float* w2    = (const float*)d_in[4];
    const float* b2    = (const float*)d_in[5];
    const float* w3    = (const float*)d_in[6];
    const float* b3    = (const float*)d_in[7];
    float* out = (float*)d_out;

    uint32_t *h1, *h2;
    float* lg;
    cudaGetSymbolAddress((void**)&h1, g_h1);
    cudaGetSymbolAddress((void**)&h2, g_h2);
    cudaGetSymbolAddress((void**)&lg, g_logits);

    cudaFuncSetAttribute(conv3x3_hmma<64, 2, true, true>,
                         cudaFuncAttributeMaxDynamicSharedMemorySize, HMMA_SMEM);
    cudaFuncSetAttribute(conv3x3_hmma<81, 3, false, false>,
                         cudaFuncAttributeMaxDynamicSharedMemorySize, HMMA_SMEM);

    // conv1: scalar FFMA2, writes split-format h1
    conv1_kernel<<<dim3(WW / 32, HH / 16, BATCH), 512>>>(rgb, depth, w1, b1, h1);
    // conv2: HMMA implicit GEMM (2 co-slices of 32), split in / split out
    conv3x3_hmma<64, 2, true, true><<<dim3(WW / NPX, HH / RPC, 2 * BATCH), 256,
                                      HMMA_SMEM>>>(h1, w2, b2, h2);
    // conv3: HMMA implicit GEMM (3 co-slices of 32, 81 real), split in / f32 out
    conv3x3_hmma<81, 3, false, false><<<dim3(WW / NPX, HH / RPC, 3 * BATCH), 256,
                                        HMMA_SMEM>>>(h2, w3, b3, lg);
    // softmax + bokeh
    softmax_bokeh_kernel<<<dim3(WW / 32, HH / 4, BATCH), 128>>>(lg, rgb, out);
}

// round 9
// speedup vs baseline: 2.1413x; 1.2463x over previous
#include <cuda_runtime.h>
#include <cuda_bf16.h>
#include <cstdint>
#include <cstddef>

#define HH 384
#define WW 384
#define BATCH 4
#define HWSZ (HH * WW)

// h1/h2 in split format: u32 = bf16(hi) | bf16(lo)<<16
__device__ uint32_t g_h1[(size_t)BATCH * 64 * HWSZ];
__device__ uint32_t g_h2[(size_t)BATCH * 64 * HWSZ];
__device__ float    g_logits[(size_t)BATCH * 81 * HWSZ];

// =============================== helpers ====================================
__device__ __forceinline__ uint32_t smem_u32(const void* p) {
    uint32_t a;
    asm("{ .reg .u64 t; cvta.to.shared.u64 t, %1; cvt.u32.u64 %0, t; }"
        : "=r"(a) : "l"(p));
    return a;
}
__device__ __forceinline__ void ldmx4(uint32_t& r0, uint32_t& r1, uint32_t& r2,
                                      uint32_t& r3, uint32_t addr) {
    asm volatile("ldmatrix.sync.aligned.m8n8.x4.shared.b16 {%0,%1,%2,%3}, [%4];"
                 : "=r"(r0), "=r"(r1), "=r"(r2), "=r"(r3) : "r"(addr));
}
__device__ __forceinline__ void mma16816(float* c, const uint32_t* a,
                                         uint32_t b0, uint32_t b1) {
    asm volatile(
        "mma.sync.aligned.m16n8k16.row.col.f32.bf16.bf16.f32 "
        "{%0,%1,%2,%3}, {%4,%5,%6,%7}, {%8,%9}, {%0,%1,%2,%3};"
        : "+f"(c[0]), "+f"(c[1]), "+f"(c[2]), "+f"(c[3])
        : "r"(a[0]), "r"(a[1]), "r"(a[2]), "r"(a[3]), "r"(b0), "r"(b1));
}
// pack two f32 -> bf16x2 (low half = f0), plus residual word
__device__ __forceinline__ void split2(float f0, float f1, uint32_t& hi,
                                       uint32_t& lo) {
    asm("cvt.rn.bf16x2.f32 %0, %1, %2;" : "=r"(hi) : "f"(f1), "f"(f0));
    float f0h = __uint_as_float(hi << 16);
    float f1h = __uint_as_float(hi & 0xFFFF0000u);
    asm("cvt.rn.bf16x2.f32 %0, %1, %2;" : "=r"(lo) : "f"(f1 - f1h), "f"(f0 - f0h));
}
// scalar split pack: u32 = bf16(v) | bf16(v - hi)<<16
__device__ __forceinline__ uint32_t pack_split(float v) {
    uint32_t h;
    asm("cvt.rn.bf16x2.f32 %0, %1, %1;" : "=r"(h) : "f"(v));
    float hf = __uint_as_float(h << 16);
    float l = v - hf;
    uint32_t lb;
    asm("cvt.rn.bf16x2.f32 %0, %1, %1;" : "=r"(lb) : "f"(l));
    return (h & 0xFFFFu) | (lb << 16);
}

// ===================== HMMA implicit-GEMM 3x3 conv ==========================
// Per CTA: co-slice M=32, px-tile N=128, persist over RPC=32 rows (2 per iter).
// 512 threads / 16 warps: warp = (wy 0..1: co-half of 16) x (wx 0..7: 16-px).
// A (weights, 9 taps, hi+lo) staged once; B (split input) ring of 4 row-planes
// x {hi,lo}, layout [px][ci] bf16, 16B-chunk XOR swizzle. Loop nest
// (kc -> dx -> planes -> dy) shares B fragments between the two output rows.
#define RPC 32
#define NPX 128
#define A_PLANE (9 * 32 * 128)
#define OFF_B   (2 * A_PLANE)              // 73728
#define B_PLANE (132 * 128)                // 16896 per (split, slot)
#define HMMA_SMEM (OFF_B + 8 * B_PLANE)    // 208896

template <int COUT, int NSLICE, bool RELU, bool PACK_OUT>
__global__ __launch_bounds__(512, 1)
void conv3x3_hmma(const uint32_t* __restrict__ in, const float* __restrict__ wgt,
                  const float* __restrict__ bias, void* __restrict__ outv) {
    extern __shared__ __align__(128) char smem[];
    const uint32_t sb = smem_u32(smem);
    const int tid = threadIdx.x, warp = tid >> 5, lane = tid & 31;
    const int x0 = blockIdx.x * NPX;
    const int y0 = blockIdx.y * RPC;
    const int mslice = blockIdx.z % NSLICE;
    const int b = blockIdx.z / NSLICE;
    const int co_base = mslice * 32;
    const int wy = warp & 1;      // co half (16)
    const int wx = warp >> 1;     // px slice (16)

    // ---- stage A: 9 taps x 32 co x 64 ci, hi+lo, swizzled [co][ci] ----
    {
        const int cpl = lane & 3, po = lane >> 2;
        for (int it = warp; it < 288; it += 16) {
            int t = it / 32, r = it & 31;
            int cotile = r >> 3, c = r & 7;
            int co = cotile * 8 + po;
            int ci0 = c * 8 + cpl * 2;
            int cog = co_base + co;
            float f0 = 0.f, f1 = 0.f;
            if (cog < COUT) {
                const float* wp = wgt + ((size_t)cog * 64 + ci0) * 9 + t;
                f0 = __ldg(wp);
                f1 = __ldg(wp + 9);
            }
            uint32_t hi, lo;
            split2(f0, f1, hi, lo);
            uint32_t off = (uint32_t)((t * 32 + co) * 128 +
                                      ((c ^ (co & 7)) << 4) + cpl * 4);
            asm volatile("st.shared.b32 [%0], %1;" :: "r"(sb + off), "r"(hi) : "memory");
            asm volatile("st.shared.b32 [%0], %1;" :: "r"(sb + A_PLANE + off), "r"(lo) : "memory");
        }
    }

    // ---- B row-plane stage: plane row yy -> slot (yy+4)&3 ----
    auto stage_B = [&](int yy) {
        const int slot = (yy + 4) & 3;
        const bool ok_row = (yy >= 0) && (yy < HH);
        const uint32_t* src = in + ((size_t)b * 64 * HH + (ok_row ? yy : 0)) * WW;
        const int cpl = lane & 3, po = lane >> 2;
        const uint32_t bH = sb + OFF_B + slot * B_PLANE;
        const uint32_t bL = sb + OFF_B + (4 + slot) * B_PLANE;
        for (int it = warp; it < 136; it += 16) {
            int c = it & 7, pxt = it >> 3;
            int px = pxt * 8 + po;
            if (px >= 132) continue;
            int ci0 = c * 8 + cpl * 2;
            int gx = x0 - 1 + px;
            bool ok = ok_row && (gx >= 0) && (gx < WW);
            const uint32_t* p = src + (size_t)ci0 * HWSZ + (ok ? gx : 0);
            uint32_t u0 = ok ? __ldg(p) : 0u;
            uint32_t u1 = ok ? __ldg(p + HWSZ) : 0u;
            uint32_t hi, lo;
            asm("prmt.b32 %0, %1, %2, 0x5410;" : "=r"(hi) : "r"(u0), "r"(u1));
            asm("prmt.b32 %0, %1, %2, 0x7632;" : "=r"(lo) : "r"(u0), "r"(u1));
            uint32_t off = (uint32_t)(px * 128 + ((c ^ (px & 7)) << 4) + cpl * 4);
            asm volatile("st.shared.b32 [%0], %1;" :: "r"(bH + off), "r"(hi) : "memory");
            asm volatile("st.shared.b32 [%0], %1;" :: "r"(bL + off), "r"(lo) : "memory");
        }
    };

    stage_B(y0 - 1);
    stage_B(y0);
    stage_B(y0 + 1);
    stage_B(y0 + 2);
    __syncthreads();

    const int r7 = lane & 7, g = lane >> 3;
    const int a_row = wy * 16 + r7 + ((g & 1) << 3);  // co row within 32
    const int a_kh = g >> 1;
    const int b_noff = r7 + ((g >> 1) << 3);
    const int b_kh = g & 1;
    const int nb = wx * 16;
    const int row_d = lane >> 2, col_d = (lane & 3) * 2;

    const int yend = y0 + RPC;
#pragma unroll 1
    for (int y = y0; y < yend; y += 2) {
        float acc[2][2][4];
#pragma unroll
        for (int r = 0; r < 2; r++)
#pragma unroll
            for (int i = 0; i < 2; i++)
#pragma unroll
                for (int j = 0; j < 4; j++) acc[r][i][j] = 0.f;

        // plane slots: index i = input row (y-1+i), i=0..3
        uint32_t plH[4], plL[4];
#pragma unroll
        for (int i = 0; i < 4; i++) {
            int slot = (y - 1 + i + 4) & 3;
            plH[i] = sb + OFF_B + slot * B_PLANE;
            plL[i] = plH[i] + 4 * B_PLANE;
        }

#pragma unroll
        for (int kc = 0; kc < 4; kc++) {
#pragma unroll
            for (int dx = 0; dx < 3; dx++) {
                const int pxm = nb + dx + b_noff;
                const uint32_t bRow = (uint32_t)(pxm * 128);
                const uint32_t cB =
                    (uint32_t)((((kc << 1) | b_kh) ^ (pxm & 7)) << 4);
                // B fragments for all 4 planes, hi+lo (8 LDSM.x4)
                uint32_t BF[4][2][4];
#pragma unroll
                for (int pl = 0; pl < 4; pl++) {
                    ldmx4(BF[pl][0][0], BF[pl][0][1], BF[pl][0][2], BF[pl][0][3],
                          plH[pl] + bRow + cB);
                    ldmx4(BF[pl][1][0], BF[pl][1][1], BF[pl][1][2], BF[pl][1][3],
                          plL[pl] + bRow + cB);
                }
                const uint32_t cA = (uint32_t)((((kc << 1) | a_kh) ^ r7) << 4);
#pragma unroll
                for (int dy = 0; dy < 3; dy++) {
                    const int t = dy * 3 + dx;
                    const uint32_t aHp = sb + (uint32_t)(t * 32 * 128);
                    const uint32_t aLp = aHp + A_PLANE;
                    uint32_t AH[4], AL[4];
                    ldmx4(AH[0], AH[1], AH[2], AH[3],
                          aHp + (uint32_t)(a_row * 128) + cA);
                    ldmx4(AL[0], AL[1], AL[2], AL[3],
                          aLp + (uint32_t)(a_row * 128) + cA);
                    // row 0 (y): plane dy; row 1 (y+1): plane dy+1
#pragma unroll
                    for (int nt = 0; nt < 2; nt++) {
                        float* c0 = acc[0][nt];
                        mma16816(c0, AH, BF[dy][0][nt * 2], BF[dy][0][nt * 2 + 1]);
                        mma16816(c0, AH, BF[dy][1][nt * 2], BF[dy][1][nt * 2 + 1]);
                        mma16816(c0, AL, BF[dy][0][nt * 2], BF[dy][0][nt * 2 + 1]);
                        float* c1 = acc[1][nt];
                        mma16816(c1, AH, BF[dy + 1][0][nt * 2], BF[dy + 1][0][nt * 2 + 1]);
                        mma16816(c1, AH, BF[dy + 1][1][nt * 2], BF[dy + 1][1][nt * 2 + 1]);
                        mma16816(c1, AL, BF[dy + 1][0][nt * 2], BF[dy + 1][0][nt * 2 + 1]);
                    }
                }
            }
        }

        // epilogue (global only, no SMEM)
#pragma unroll
        for (int r = 0; r < 2; r++) {
            const int yy = y + r;
#pragma unroll
            for (int nt = 0; nt < 2; nt++) {
                float* c = acc[r][nt];
                int x = x0 + nb + nt * 8 + col_d;
#pragma unroll
                for (int h = 0; h < 2; h++) {
                    int co = co_base + wy * 16 + row_d + h * 8;
                    if (co < COUT) {
                        float bv = __ldg(bias + co);
                        float v0 = c[2 * h] + bv, v1 = c[2 * h + 1] + bv;
                        if (RELU) { v0 = fmaxf(v0, 0.f); v1 = fmaxf(v1, 0.f); }
                        size_t idx = (((size_t)b * COUT + co) * HH + yy) * WW + x;
                        if (PACK_OUT) {
                            uint2 u = make_uint2(pack_split(v0), pack_split(v1));
                            *reinterpret_cast<uint2*>((uint32_t*)outv + idx) = u;
                        } else {
                            *reinterpret_cast<float2*>((float*)outv + idx) =
                                make_float2(v0, v1);
                        }
                    }
                }
            }
        }

        if (y + 2 < yend) {
            __syncthreads();
            stage_B(y + 3);
            stage_B(y + 4);
            __syncthreads();
        }
    }
}

// ======================= scalar conv1 (4 -> 64) =============================
__device__ __forceinline__ unsigned long long pack2(float x, float y) {
    unsigned long long r;
    asm("mov.b64 %0, {%1, %2};" : "=l"(r) : "f"(x), "f"(y));
    return r;
}
__device__ __forceinline__ unsigned long long bcast2(float x) { return pack2(x, x); }
__device__ __forceinline__ float2 unpack2(unsigned long long v) {
    float2 f;
    asm("mov.b64 {%0, %1}, %2;" : "=f"(f.x), "=f"(f.y) : "l"(v));
    return f;
}
__device__ __forceinline__ unsigned long long ffma2(unsigned long long a,
                                                    unsigned long long b,
                                                    unsigned long long c) {
    unsigned long long d;
    asm("fma.rn.f32x2 %0, %1, %2, %3;" : "=l"(d) : "l"(a), "l"(b), "l"(c));
    return d;
}

__global__ __launch_bounds__(512, 1)
void conv1_kernel(const float* __restrict__ rgb, const float* __restrict__ depth,
                  const float* __restrict__ wgt, const float* __restrict__ bias,
                  uint32_t* __restrict__ out) {
    constexpr int QS = 16, PIX = 4, CCH = 4;
    constexpr int NP = 8, NP2 = 4;
    __shared__ __align__(16) float ws[CCH][9][4][QS];

    const int tid = threadIdx.x;
    const int lx = tid & 31;
    const int ty = (tid >> 5) & 3;
    const int q = tid >> 7;
    const int x = blockIdx.x * 32 + lx;
    const int y0 = blockIdx.y * (4 * PIX) + ty * PIX;
    const int b = blockIdx.z;
    const int co0 = q * QS;

    unsigned long long acc[PIX][NP];
#pragma unroll
    for (int pr = 0; pr < NP; pr++) {
        unsigned long long bb = pack2(__ldg(bias + co0 + 2 * pr),
                                      __ldg(bias + co0 + 2 * pr + 1));
#pragma unroll
        for (int p = 0; p < PIX; p++) acc[p][pr] = bb;
    }

    int rowoff[PIX + 2];
    bool rok[PIX + 2];
#pragma unroll
    for (int r = 0; r < PIX + 2; r++) {
        int yy = y0 - 1 + r;
        rok[r] = (yy >= 0) && (yy < HH);
        rowoff[r] = yy * WW;
    }
    const bool xok0 = (x > 0), xok2 = (x < WW - 1);

    for (int i = tid; i < CCH * 9 * 4 * QS; i += 512) {
        int col = i % QS;
        int qq = (i / QS) % 4;
        int t = (i / (QS * 4)) % 9;
        int cl = i / (QS * 4 * 9);
        (&ws[0][0][0][0])[i] = __ldg(wgt + ((size_t)(qq * QS + col) * 4 + cl) * 9 + t);
    }
    __syncthreads();

#pragma unroll
    for (int ci = 0; ci < 4; ci++) {
        const float* ip = (ci < 3) ? (rgb + ((size_t)b * 3 + ci) * HWSZ)
                                   : (depth + (size_t)b * HWSZ);
        const float* ipx = ip + x;
        float v[PIX + 2][3];
#pragma unroll
        for (int r = 0; r < PIX + 2; r++) {
            v[r][0] = (rok[r] && xok0) ? __ldg(ipx + rowoff[r] - 1) : 0.f;
            v[r][1] = rok[r] ? __ldg(ipx + rowoff[r]) : 0.f;
            v[r][2] = (rok[r] && xok2) ? __ldg(ipx + rowoff[r] + 1) : 0.f;
        }
#pragma unroll
        for (int dy = 0; dy < 3; dy++) {
#pragma unroll
            for (int dx = 0; dx < 3; dx++) {
                const ulonglong2* wp =
                    reinterpret_cast<const ulonglong2*>(&ws[ci][dy * 3 + dx][q][0]);
                ulonglong2 wq[NP2];
#pragma unroll
                for (int j = 0; j < NP2; j++) wq[j] = wp[j];
#pragma unroll
                for (int p = 0; p < PIX; p++) {
                    unsigned long long vv = bcast2(v[p + dy][dx]);
#pragma unroll
                    for (int j = 0; j < NP2; j++) {
                        acc[p][2 * j] = ffma2(vv, wq[j].x, acc[p][2 * j]);
                        acc[p][2 * j + 1] = ffma2(vv, wq[j].y, acc[p][2 * j + 1]);
                    }
                }
            }
        }
    }

#pragma unroll
    for (int p = 0; p < PIX; p++) {
        size_t base = ((size_t)b * 64) * HWSZ + (size_t)(y0 + p) * WW + x;
#pragma unroll
        for (int pr = 0; pr < NP; pr++) {
            float2 f = unpack2(acc[p][pr]);
            f.x = fmaxf(f.x, 0.f);
            f.y = fmaxf(f.y, 0.f);
            int co = co0 + 2 * pr;
            out[base + (size_t)co * HWSZ] = pack_split(f.x);
            out[base + (size_t)(co + 1) * HWSZ] = pack_split(f.y);
        }
    }
}

// ======================= softmax + bokeh ====================================
__global__ __launch_bounds__(128, 4)
void softmax_bokeh_kernel(const float* __restrict__ logits,
                          const float* __restrict__ rgb,
                          float* __restrict__ out) {
    __shared__ float tile[3][12][40];
    const int tid = threadIdx.x;
    const int lx = tid & 31;
    const int ty = tid >> 5;
    const int x = blockIdx.x * 32 + lx;
    const int y = blockIdx.y * 4 + ty;
    const int b = blockIdx.z;
    const int gx0 = blockIdx.x * 32 - 4;
    const int gy0 = blockIdx.y * 4 - 4;

    for (int i = tid; i < 3 * 12 * 40; i += 128) {
        int xx = i % 40;
        int yy = (i / 40) % 12;
        int c = i / 480;
        int gx = gx0 + xx, gy = gy0 + yy;
        float v = 0.f;
        if (gx >= 0 && gx < WW && gy >= 0 && gy < HH)
            v = rgb[((size_t)b * 3 + c) * HWSZ + (size_t)gy * WW + gx];
        tile[c][yy][xx] = v;
    }
    __syncthreads();

    float lg[81];
    const float* lp = logits + (size_t)b * 81 * HWSZ + (size_t)y * WW + x;
    float m = -1e30f;
#pragma unroll
    for (int t = 0; t < 81; t++) {
        lg[t] = __ldg(lp + (size_t)t * HWSZ);
        m = fmaxf(m, lg[t]);
    }
    float s = 0.f;
#pragma unroll
    for (int t = 0; t < 81; t++) {
        float e = __expf(lg[t] - m);
        lg[t] = e;
        s += e;
    }
    float inv = 1.f / s;

    float r = 0.f, g = 0.f, bl = 0.f;
#pragma unroll
    for (int dy = 0; dy < 9; dy++) {
#pragma unroll
        for (int dx = 0; dx < 9; dx++) {
            float f = lg[dy * 9 + dx] * inv;
            r += f * tile[0][ty + dy][lx + dx];
            g += f * tile[1][ty + dy][lx + dx];
            bl += f * tile[2][ty + dy][lx + dx];
        }
    }
    size_t ob = (size_t)b * 3 * HWSZ + (size_t)y * WW + x;
    out[ob] = r;
    out[ob + HWSZ] = g;
    out[ob + 2 * HWSZ] = bl;
}

// ======================= launch =============================================
extern "C" void kernel_launch(void* const* d_in, const int* in_sizes, int n_in,
                              void* d_out, int out_size) {
    const float* rgb   = (const float*)d_in[0];
    const float* depth = (const float*)d_in[1];
    const float* w1    = (const float*)d_in[2];
    const float* b1    = (const float*)d_in[3];
    const float* w2    = (const float*)d_in[4];
    const float* b2    = (const float*)d_in[5];
    const float* w3    = (const float*)d_in[6];
    const float* b3    = (const float*)d_in[7];
    float* out = (float*)d_out;

    uint32_t *h1, *h2;
    float* lg;
    cudaGetSymbolAddress((void**)&h1, g_h1);
    cudaGetSymbolAddress((void**)&h2, g_h2);
    cudaGetSymbolAddress((void**)&lg, g_logits);

    cudaFuncSetAttribute(conv3x3_hmma<64, 2, true, true>,
                         cudaFuncAttributeMaxDynamicSharedMemorySize, HMMA_SMEM);
    cudaFuncSetAttribute(conv3x3_hmma<81, 3, false, false>,
                         cudaFuncAttributeMaxDynamicSharedMemorySize, HMMA_SMEM);

    // conv1: scalar FFMA2, writes split-format h1
    conv1_kernel<<<dim3(WW / 32, HH / 16, BATCH), 512>>>(rgb, depth, w1, b1, h1);
    // conv2: HMMA implicit GEMM (2 co-slices of 32), split in / split out
    conv3x3_hmma<64, 2, true, true><<<dim3(WW / NPX, HH / RPC, 2 * BATCH), 512,
                                      HMMA_SMEM>>>(h1, w2, b2, h2);
    // conv3: HMMA implicit GEMM (3 co-slices of 32, 81 real), split in / f32 out
    conv3x3_hmma<81, 3, false, false><<<dim3(WW / NPX, HH / RPC, 3 * BATCH), 512,
                                        HMMA_SMEM>>>(h2, w3, b3, lg);
    // softmax + bokeh
    softmax_bokeh_kernel<<<dim3(WW / 32, HH / 4, BATCH), 128>>>(lg, rgb, out);
}

// round 10
// speedup vs baseline: 2.3083x; 1.0780x over previous
#include <cuda_runtime.h>
#include <cuda_bf16.h>
#include <cstdint>
#include <cstddef>

#define HH 384
#define WW 384
#define BATCH 4
#define HWSZ (HH * WW)

// h1/h2 in split format: u32 = bf16(hi) | bf16(lo)<<16
__device__ uint32_t g_h1[(size_t)BATCH * 64 * HWSZ];
__device__ uint32_t g_h2[(size_t)BATCH * 64 * HWSZ];
__device__ float    g_logits[(size_t)BATCH * 81 * HWSZ];

// =============================== helpers ====================================
__device__ __forceinline__ uint32_t smem_u32(const void* p) {
    uint32_t a;
    asm("{ .reg .u64 t; cvta.to.shared.u64 t, %1; cvt.u32.u64 %0, t; }"
        : "=r"(a) : "l"(p));
    return a;
}
__device__ __forceinline__ void ldmx4(uint32_t& r0, uint32_t& r1, uint32_t& r2,
                                      uint32_t& r3, uint32_t addr) {
    asm volatile("ldmatrix.sync.aligned.m8n8.x4.shared.b16 {%0,%1,%2,%3}, [%4];"
                 : "=r"(r0), "=r"(r1), "=r"(r2), "=r"(r3) : "r"(addr));
}
__device__ __forceinline__ void ldmx2(uint32_t& r0, uint32_t& r1, uint32_t addr) {
    asm volatile("ldmatrix.sync.aligned.m8n8.x2.shared.b16 {%0,%1}, [%2];"
                 : "=r"(r0), "=r"(r1) : "r"(addr));
}
__device__ __forceinline__ void mma16816(float* c, const uint32_t* a,
                                         uint32_t b0, uint32_t b1) {
    asm volatile(
        "mma.sync.aligned.m16n8k16.row.col.f32.bf16.bf16.f32 "
        "{%0,%1,%2,%3}, {%4,%5,%6,%7}, {%8,%9}, {%0,%1,%2,%3};"
        : "+f"(c[0]), "+f"(c[1]), "+f"(c[2]), "+f"(c[3])
        : "r"(a[0]), "r"(a[1]), "r"(a[2]), "r"(a[3]), "r"(b0), "r"(b1));
}
// pack two f32 -> bf16x2 (low half = f0), plus residual word
__device__ __forceinline__ void split2(float f0, float f1, uint32_t& hi,
                                       uint32_t& lo) {
    asm("cvt.rn.bf16x2.f32 %0, %1, %2;" : "=r"(hi) : "f"(f1), "f"(f0));
    float f0h = __uint_as_float(hi << 16);
    float f1h = __uint_as_float(hi & 0xFFFF0000u);
    asm("cvt.rn.bf16x2.f32 %0, %1, %2;" : "=r"(lo) : "f"(f1 - f1h), "f"(f0 - f0h));
}
// scalar split pack: u32 = bf16(v) | bf16(v - hi)<<16
__device__ __forceinline__ uint32_t pack_split(float v) {
    uint32_t h;
    asm("cvt.rn.bf16x2.f32 %0, %1, %1;" : "=r"(h) : "f"(v));
    float hf = __uint_as_float(h << 16);
    float l = v - hf;
    uint32_t lb;
    asm("cvt.rn.bf16x2.f32 %0, %1, %1;" : "=r"(lb) : "f"(l));
    return (h & 0xFFFFu) | (lb << 16);
}

// ===================== HMMA implicit-GEMM 3x3 conv ==========================
// Per CTA: co-slice M=32, px-tile N=128, persist over RPC=32 rows (2 per iter).
// 1024 threads / 32 warps: warp = (wy 0..1: co-half of 16) x (wx 0..15: 8-px).
// A (weights, 9 taps, hi+lo) staged once; B (split input) ring of 4 row-planes
// x {hi,lo}, layout [px][ci] bf16, 16B-chunk XOR swizzle. Loop nest
// (kc -> dx -> planes -> dy) shares B fragments between the two output rows.
#define RPC 32
#define NPX 128
#define A_PLANE (9 * 32 * 128)
#define OFF_B   (2 * A_PLANE)              // 73728
#define B_PLANE (132 * 128)                // 16896 per (split, slot)
#define HMMA_SMEM (OFF_B + 8 * B_PLANE)    // 208896
#define NTHREADS 1024
#define NWARPS 32

template <int COUT, int NSLICE, bool RELU, bool PACK_OUT>
__global__ __launch_bounds__(NTHREADS, 1)
void conv3x3_hmma(const uint32_t* __restrict__ in, const float* __restrict__ wgt,
                  const float* __restrict__ bias, void* __restrict__ outv) {
    extern __shared__ __align__(128) char smem[];
    const uint32_t sb = smem_u32(smem);
    const int tid = threadIdx.x, warp = tid >> 5, lane = tid & 31;
    const int x0 = blockIdx.x * NPX;
    const int y0 = blockIdx.y * RPC;
    const int mslice = blockIdx.z % NSLICE;
    const int b = blockIdx.z / NSLICE;
    const int co_base = mslice * 32;
    const int wy = warp & 1;      // co half (16)
    const int wx = warp >> 1;     // px slice (8)

    // ---- stage A: 9 taps x 32 co x 64 ci, hi+lo, swizzled [co][ci] ----
    {
        const int cpl = lane & 3, po = lane >> 2;
        for (int it = warp; it < 288; it += NWARPS) {
            int t = it / 32, r = it & 31;
            int cotile = r >> 3, c = r & 7;
            int co = cotile * 8 + po;
            int ci0 = c * 8 + cpl * 2;
            int cog = co_base + co;
            float f0 = 0.f, f1 = 0.f;
            if (cog < COUT) {
                const float* wp = wgt + ((size_t)cog * 64 + ci0) * 9 + t;
                f0 = __ldg(wp);
                f1 = __ldg(wp + 9);
            }
            uint32_t hi, lo;
            split2(f0, f1, hi, lo);
            uint32_t off = (uint32_t)((t * 32 + co) * 128 +
                                      ((c ^ (co & 7)) << 4) + cpl * 4);
            asm volatile("st.shared.b32 [%0], %1;" :: "r"(sb + off), "r"(hi) : "memory");
            asm volatile("st.shared.b32 [%0], %1;" :: "r"(sb + A_PLANE + off), "r"(lo) : "memory");
        }
    }

    // ---- B row-plane stage: plane row yy -> slot (yy+4)&3 ----
    auto stage_B = [&](int yy) {
        const int slot = (yy + 4) & 3;
        const bool ok_row = (yy >= 0) && (yy < HH);
        const uint32_t* src = in + ((size_t)b * 64 * HH + (ok_row ? yy : 0)) * WW;
        const int cpl = lane & 3, po = lane >> 2;
        const uint32_t bH = sb + OFF_B + slot * B_PLANE;
        const uint32_t bL = sb + OFF_B + (4 + slot) * B_PLANE;
        for (int it = warp; it < 136; it += NWARPS) {
            int c = it & 7, pxt = it >> 3;
            int px = pxt * 8 + po;
            if (px >= 132) continue;
            int ci0 = c * 8 + cpl * 2;
            int gx = x0 - 1 + px;
            bool ok = ok_row && (gx >= 0) && (gx < WW);
            const uint32_t* p = src + (size_t)ci0 * HWSZ + (ok ? gx : 0);
            uint32_t u0 = ok ? __ldg(p) : 0u;
            uint32_t u1 = ok ? __ldg(p + HWSZ) : 0u;
            uint32_t hi, lo;
            asm("prmt.b32 %0, %1, %2, 0x5410;" : "=r"(hi) : "r"(u0), "r"(u1));
            asm("prmt.b32 %0, %1, %2, 0x7632;" : "=r"(lo) : "r"(u0), "r"(u1));
            uint32_t off = (uint32_t)(px * 128 + ((c ^ (px & 7)) << 4) + cpl * 4);
            asm volatile("st.shared.b32 [%0], %1;" :: "r"(bH + off), "r"(hi) : "memory");
            asm volatile("st.shared.b32 [%0], %1;" :: "r"(bL + off), "r"(lo) : "memory");
        }
    };

    stage_B(y0 - 1);
    stage_B(y0);
    stage_B(y0 + 1);
    stage_B(y0 + 2);
    __syncthreads();

    const int r7 = lane & 7, g = lane >> 3;
    const int a_row = wy * 16 + r7 + ((g & 1) << 3);  // co row within 32
    const int a_kh = g >> 1;
    // B ldmatrix.x2: addresses from lanes 0-15; g=0 -> kh0, g=1 -> kh1
    const int b_noff = r7;
    const int b_kh = g & 1;
    const int nb = wx * 8;
    const int row_d = lane >> 2, col_d = (lane & 3) * 2;

    const int yend = y0 + RPC;
#pragma unroll 1
    for (int y = y0; y < yend; y += 2) {
        float acc[2][4];
#pragma unroll
        for (int r = 0; r < 2; r++)
#pragma unroll
            for (int j = 0; j < 4; j++) acc[r][j] = 0.f;

        // plane slots: index i = input row (y-1+i), i=0..3
        uint32_t plH[4], plL[4];
#pragma unroll
        for (int i = 0; i < 4; i++) {
            int slot = (y - 1 + i + 4) & 3;
            plH[i] = sb + OFF_B + slot * B_PLANE;
            plL[i] = plH[i] + 4 * B_PLANE;
        }

#pragma unroll
        for (int kc = 0; kc < 4; kc++) {
#pragma unroll
            for (int dx = 0; dx < 3; dx++) {
                const int pxm = nb + dx + b_noff;
                const uint32_t bRow = (uint32_t)(pxm * 128);
                const uint32_t cB =
                    (uint32_t)((((kc << 1) | b_kh) ^ (pxm & 7)) << 4);
                // B n8 fragments for all 4 planes, hi+lo (8 LDSM.x2)
                uint32_t BF[4][2][2];
#pragma unroll
                for (int pl = 0; pl < 4; pl++) {
                    ldmx2(BF[pl][0][0], BF[pl][0][1], plH[pl] + bRow + cB);
                    ldmx2(BF[pl][1][0], BF[pl][1][1], plL[pl] + bRow + cB);
                }
                const uint32_t cA = (uint32_t)((((kc << 1) | a_kh) ^ r7) << 4);
#pragma unroll
                for (int dy = 0; dy < 3; dy++) {
                    const int t = dy * 3 + dx;
                    const uint32_t aHp = sb + (uint32_t)(t * 32 * 128);
                    const uint32_t aLp = aHp + A_PLANE;
                    uint32_t AH[4], AL[4];
                    ldmx4(AH[0], AH[1], AH[2], AH[3],
                          aHp + (uint32_t)(a_row * 128) + cA);
                    ldmx4(AL[0], AL[1], AL[2], AL[3],
                          aLp + (uint32_t)(a_row * 128) + cA);
                    // row 0 (y): plane dy; row 1 (y+1): plane dy+1
                    mma16816(acc[0], AH, BF[dy][0][0], BF[dy][0][1]);
                    mma16816(acc[0], AH, BF[dy][1][0], BF[dy][1][1]);
                    mma16816(acc[0], AL, BF[dy][0][0], BF[dy][0][1]);
                    mma16816(acc[1], AH, BF[dy + 1][0][0], BF[dy + 1][0][1]);
                    mma16816(acc[1], AH, BF[dy + 1][1][0], BF[dy + 1][1][1]);
                    mma16816(acc[1], AL, BF[dy + 1][0][0], BF[dy + 1][0][1]);
                }
            }
        }

        // epilogue (global only, no SMEM)
#pragma unroll
        for (int r = 0; r < 2; r++) {
            const int yy = y + r;
            float* c = acc[r];
            int x = x0 + nb + col_d;
#pragma unroll
            for (int h = 0; h < 2; h++) {
                int co = co_base + wy * 16 + row_d + h * 8;
                if (co < COUT) {
                    float bv = __ldg(bias + co);
                    float v0 = c[2 * h] + bv, v1 = c[2 * h + 1] + bv;
                    if (RELU) { v0 = fmaxf(v0, 0.f); v1 = fmaxf(v1, 0.f); }
                    size_t idx = (((size_t)b * COUT + co) * HH + yy) * WW + x;
                    if (PACK_OUT) {
                        uint2 u = make_uint2(pack_split(v0), pack_split(v1));
                        *reinterpret_cast<uint2*>((uint32_t*)outv + idx) = u;
                    } else {
                        *reinterpret_cast<float2*>((float*)outv + idx) =
                            make_float2(v0, v1);
                    }
                }
            }
        }

        if (y + 2 < yend) {
            __syncthreads();
            stage_B(y + 3);
            stage_B(y + 4);
            __syncthreads();
        }
    }
}

// ======================= scalar conv1 (4 -> 64) =============================
__device__ __forceinline__ unsigned long long pack2(float x, float y) {
    unsigned long long r;
    asm("mov.b64 %0, {%1, %2};" : "=l"(r) : "f"(x), "f"(y));
    return r;
}
__device__ __forceinline__ unsigned long long bcast2(float x) { return pack2(x, x); }
__device__ __forceinline__ float2 unpack2(unsigned long long v) {
    float2 f;
    asm("mov.b64 {%0, %1}, %2;" : "=f"(f.x), "=f"(f.y) : "l"(v));
    return f;
}
__device__ __forceinline__ unsigned long long ffma2(unsigned long long a,
                                                    unsigned long long b,
                                                    unsigned long long c) {
    unsigned long long d;
    asm("fma.rn.f32x2 %0, %1, %2, %3;" : "=l"(d) : "l"(a), "l"(b), "l"(c));
    return d;
}

__global__ __launch_bounds__(512, 1)
void conv1_kernel(const float* __restrict__ rgb, const float* __restrict__ depth,
                  const float* __restrict__ wgt, const float* __restrict__ bias,
                  uint32_t* __restrict__ out) {
    constexpr int QS = 16, PIX = 4, CCH = 4;
    constexpr int NP = 8, NP2 = 4;
    __shared__ __align__(16) float ws[CCH][9][4][QS];

    const int tid = threadIdx.x;
    const int lx = tid & 31;
    const int ty = (tid >> 5) & 3;
    const int q = tid >> 7;
    const int x = blockIdx.x * 32 + lx;
    const int y0 = blockIdx.y * (4 * PIX) + ty * PIX;
    const int b = blockIdx.z;
    const int co0 = q * QS;

    unsigned long long acc[PIX][NP];
#pragma unroll
    for (int pr = 0; pr < NP; pr++) {
        unsigned long long bb = pack2(__ldg(bias + co0 + 2 * pr),
                                      __ldg(bias + co0 + 2 * pr + 1));
#pragma unroll
        for (int p = 0; p < PIX; p++) acc[p][pr] = bb;
    }

    int rowoff[PIX + 2];
    bool rok[PIX + 2];
#pragma unroll
    for (int r = 0; r < PIX + 2; r++) {
        int yy = y0 - 1 + r;
        rok[r] = (yy >= 0) && (yy < HH);
        rowoff[r] = yy * WW;
    }
    const bool xok0 = (x > 0), xok2 = (x < WW - 1);

    for (int i = tid; i < CCH * 9 * 4 * QS; i += 512) {
        int col = i % QS;
        int qq = (i / QS) % 4;
        int t = (i / (QS * 4)) % 9;
        int cl = i / (QS * 4 * 9);
        (&ws[0][0][0][0])[i] = __ldg(wgt + ((size_t)(qq * QS + col) * 4 + cl) * 9 + t);
    }
    __syncthreads();

#pragma unroll
    for (int ci = 0; ci < 4; ci++) {
        const float* ip = (ci < 3) ? (rgb + ((size_t)b * 3 + ci) * HWSZ)
                                   : (depth + (size_t)b * HWSZ);
        const float* ipx = ip + x;
        float v[PIX + 2][3];
#pragma unroll
        for (int r = 0; r < PIX + 2; r++) {
            v[r][0] = (rok[r] && xok0) ? __ldg(ipx + rowoff[r] - 1) : 0.f;
            v[r][1] = rok[r] ? __ldg(ipx + rowoff[r]) : 0.f;
            v[r][2] = (rok[r] && xok2) ? __ldg(ipx + rowoff[r] + 1) : 0.f;
        }
#pragma unroll
        for (int dy = 0; dy < 3; dy++) {
#pragma unroll
            for (int dx = 0; dx < 3; dx++) {
                const ulonglong2* wp =
                    reinterpret_cast<const ulonglong2*>(&ws[ci][dy * 3 + dx][q][0]);
                ulonglong2 wq[NP2];
#pragma unroll
                for (int j = 0; j < NP2; j++) wq[j] = wp[j];
#pragma unroll
                for (int p = 0; p < PIX; p++) {
                    unsigned long long vv = bcast2(v[p + dy][dx]);
#pragma unroll
                    for (int j = 0; j < NP2; j++) {
                        acc[p][2 * j] = ffma2(vv, wq[j].x, acc[p][2 * j]);
                        acc[p][2 * j + 1] = ffma2(vv, wq[j].y, acc[p][2 * j + 1]);
                    }
                }
            }
        }
    }

#pragma unroll
    for (int p = 0; p < PIX; p++) {
        size_t base = ((size_t)b * 64) * HWSZ + (size_t)(y0 + p) * WW + x;
#pragma unroll
        for (int pr = 0; pr < NP; pr++) {
            float2 f = unpack2(acc[p][pr]);
            f.x = fmaxf(f.x, 0.f);
            f.y = fmaxf(f.y, 0.f);
            int co = co0 + 2 * pr;
            out[base + (size_t)co * HWSZ] = pack_split(f.x);
            out[base + (size_t)(co + 1) * HWSZ] = pack_split(f.y);
        }
    }
}

// ======================= softmax + bokeh ====================================
__global__ __launch_bounds__(128, 4)
void softmax_bokeh_kernel(const float* __restrict__ logits,
                          const float* __restrict__ rgb,
                          float* __restrict__ out) {
    __shared__ float tile[3][12][40];
    const int tid = threadIdx.x;
    const int lx = tid & 31;
    const int ty = tid >> 5;
    const int x = blockIdx.x * 32 + lx;
    const int y = blockIdx.y * 4 + ty;
    const int b = blockIdx.z;
    const int gx0 = blockIdx.x * 32 - 4;
    const int gy0 = blockIdx.y * 4 - 4;

    for (int i = tid; i < 3 * 12 * 40; i += 128) {
        int xx = i % 40;
        int yy = (i / 40) % 12;
        int c = i / 480;
        int gx = gx0 + xx, gy = gy0 + yy;
        float v = 0.f;
        if (gx >= 0 && gx < WW && gy >= 0 && gy < HH)
            v = rgb[((size_t)b * 3 + c) * HWSZ + (size_t)gy * WW + gx];
        tile[c][yy][xx] = v;
    }
    __syncthreads();

    float lg[81];
    const float* lp = logits + (size_t)b * 81 * HWSZ + (size_t)y * WW + x;
    float m = -1e30f;
#pragma unroll
    for (int t = 0; t < 81; t++) {
        lg[t] = __ldg(lp + (size_t)t * HWSZ);
        m = fmaxf(m, lg[t]);
    }
    float s = 0.f;
#pragma unroll
    for (int t = 0; t < 81; t++) {
        float e = __expf(lg[t] - m);
        lg[t] = e;
        s += e;
    }
    float inv = 1.f / s;

    float r = 0.f, g = 0.f, bl = 0.f;
#pragma unroll
    for (int dy = 0; dy < 9; dy++) {
#pragma unroll
        for (int dx = 0; dx < 9; dx++) {
            float f = lg[dy * 9 + dx] * inv;
            r += f * tile[0][ty + dy][lx + dx];
            g += f * tile[1][ty + dy][lx + dx];
            bl += f * tile[2][ty + dy][lx + dx];
        }
    }
    size_t ob = (size_t)b * 3 * HWSZ + (size_t)y * WW + x;
    out[ob] = r;
    out[ob + HWSZ] = g;
    out[ob + 2 * HWSZ] = bl;
}

// ======================= launch =============================================
extern "C" void kernel_launch(void* const* d_in, const int* in_sizes, int n_in,
                              void* d_out, int out_size) {
    const float* rgb   = (const float*)d_in[0];
    const float* depth = (const float*)d_in[1];
    const float* w1    = (const float*)d_in[2];
    const float* b1    = (const float*)d_in[3];
    const float* w2    = (const float*)d_in[4];
    const float* b2    = (const float*)d_in[5];
    const float* w3    = (const float*)d_in[6];
    const float* b3    = (const float*)d_in[7];
    float* out = (float*)d_out;

    uint32_t *h1, *h2;
    float* lg;
    cudaGetSymbolAddress((void**)&h1, g_h1);
    cudaGetSymbolAddress((void**)&h2, g_h2);
    cudaGetSymbolAddress((void**)&lg, g_logits);

    cudaFuncSetAttribute(conv3x3_hmma<64, 2, true, true>,
                         cudaFuncAttributeMaxDynamicSharedMemorySize, HMMA_SMEM);
    cudaFuncSetAttribute(conv3x3_hmma<81, 3, false, false>,
                         cudaFuncAttributeMaxDynamicSharedMemorySize, HMMA_SMEM);

    // conv1: scalar FFMA2, writes split-format h1
    conv1_kernel<<<dim3(WW / 32, HH / 16, BATCH), 512>>>(rgb, depth, w1, b1, h1);
    // conv2: HMMA implicit GEMM (2 co-slices of 32), split in / split out
    conv3x3_hmma<64, 2, true, true><<<dim3(WW / NPX, HH / RPC, 2 * BATCH),
                                      NTHREADS, HMMA_SMEM>>>(h1, w2, b2, h2);
    // conv3: HMMA implicit GEMM (3 co-slices of 32, 81 real), split in / f32 out
    conv3x3_hmma<81, 3, false, false><<<dim3(WW / NPX, HH / RPC, 3 * BATCH),
                                        NTHREADS, HMMA_SMEM>>>(h2, w3, b3, lg);
    // softmax + bokeh
    softmax_bokeh_kernel<<<dim3(WW / 32, HH / 4, BATCH), 128>>>(lg, rgb, out);
}

// round 11
// speedup vs baseline: 2.7219x; 1.1792x over previous
#include <cuda_runtime.h>
#include <cuda_fp16.h>
#include <cstdint>
#include <cstddef>

#define HH 384
#define WW 384
#define BATCH 4
#define HWSZ (HH * WW)

// h1/h2 in split format: u32 = fp16(hi) | fp16(residual)<<16
__device__ uint32_t g_h1[(size_t)BATCH * 64 * HWSZ];
__device__ uint32_t g_h2[(size_t)BATCH * 64 * HWSZ];
__device__ float    g_logits[(size_t)BATCH * 81 * HWSZ];

// =============================== helpers ====================================
__device__ __forceinline__ uint32_t smem_u32(const void* p) {
    uint32_t a;
    asm("{ .reg .u64 t; cvta.to.shared.u64 t, %1; cvt.u32.u64 %0, t; }"
        : "=r"(a) : "l"(p));
    return a;
}
__device__ __forceinline__ void ldmx4(uint32_t& r0, uint32_t& r1, uint32_t& r2,
                                      uint32_t& r3, uint32_t addr) {
    asm volatile("ldmatrix.sync.aligned.m8n8.x4.shared.b16 {%0,%1,%2,%3}, [%4];"
                 : "=r"(r0), "=r"(r1), "=r"(r2), "=r"(r3) : "r"(addr));
}
__device__ __forceinline__ void ldmx2(uint32_t& r0, uint32_t& r1, uint32_t addr) {
    asm volatile("ldmatrix.sync.aligned.m8n8.x2.shared.b16 {%0,%1}, [%2];"
                 : "=r"(r0), "=r"(r1) : "r"(addr));
}
__device__ __forceinline__ void mma16816(float* c, const uint32_t* a,
                                         uint32_t b0, uint32_t b1) {
    asm volatile(
        "mma.sync.aligned.m16n8k16.row.col.f32.f16.f16.f32 "
        "{%0,%1,%2,%3}, {%4,%5,%6,%7}, {%8,%9}, {%0,%1,%2,%3};"
        : "+f"(c[0]), "+f"(c[1]), "+f"(c[2]), "+f"(c[3])
        : "r"(a[0]), "r"(a[1]), "r"(a[2]), "r"(a[3]), "r"(b0), "r"(b1));
}
// pack two f32 -> fp16x2 (low half = f0)
__device__ __forceinline__ uint32_t packh2(float f0, float f1) {
    uint32_t h;
    asm("cvt.rn.f16x2.f32 %0, %1, %2;" : "=r"(h) : "f"(f1), "f"(f0));
    return h;
}
// scalar split pack: u32 = fp16(v) | fp16(v - hi)<<16
__device__ __forceinline__ uint32_t pack_split(float v) {
    __half hh = __float2half_rn(v);
    float hf = __half2float(hh);
    __half ll = __float2half_rn(v - hf);
    return (uint32_t)__half_as_ushort(hh) | ((uint32_t)__half_as_ushort(ll) << 16);
}

// ===================== HMMA implicit-GEMM 3x3 conv ==========================
// fp16 2-product scheme: weights fp16 (single rounding), activations split
// fp16 hi+lo. C = W*XH + W*XL. MMA volume 2/3 of bf16x3.
// Per CTA: co-slice M=32, px-tile N=128, persist over RPC=32 rows (2 per iter).
// 1024 threads / 32 warps: warp = (wy 0..1: co-half of 16) x (wx 0..15: 8-px).
#define RPC 32
#define NPX 128
#define A_PLANE (9 * 32 * 128)             // 36864 (fp16 weights, single plane)
#define OFF_B   A_PLANE
#define B_PLANE (132 * 128)                // 16896 per (split, slot)
#define HMMA_SMEM (OFF_B + 8 * B_PLANE)    // 172032
#define NTHREADS 1024
#define NWARPS 32

template <int COUT, int NSLICE, bool RELU, bool PACK_OUT>
__global__ __launch_bounds__(NTHREADS, 1)
void conv3x3_hmma(const uint32_t* __restrict__ in, const float* __restrict__ wgt,
                  const float* __restrict__ bias, void* __restrict__ outv) {
    extern __shared__ __align__(128) char smem[];
    const uint32_t sb = smem_u32(smem);
    const int tid = threadIdx.x, warp = tid >> 5, lane = tid & 31;
    const int x0 = blockIdx.x * NPX;
    const int y0 = blockIdx.y * RPC;
    const int mslice = blockIdx.z % NSLICE;
    const int b = blockIdx.z / NSLICE;
    const int co_base = mslice * 32;
    const int wy = warp & 1;      // co half (16)
    const int wx = warp >> 1;     // px slice (8)

    // ---- stage A: 9 taps x 32 co x 64 ci fp16, swizzled [co][ci] ----
    {
        const int cpl = lane & 3, po = lane >> 2;
        for (int it = warp; it < 288; it += NWARPS) {
            int t = it / 32, r = it & 31;
            int cotile = r >> 3, c = r & 7;
            int co = cotile * 8 + po;
            int ci0 = c * 8 + cpl * 2;
            int cog = co_base + co;
            float f0 = 0.f, f1 = 0.f;
            if (cog < COUT) {
                const float* wp = wgt + ((size_t)cog * 64 + ci0) * 9 + t;
                f0 = __ldg(wp);
                f1 = __ldg(wp + 9);
            }
            uint32_t h = packh2(f0, f1);
            uint32_t off = (uint32_t)((t * 32 + co) * 128 +
                                      ((c ^ (co & 7)) << 4) + cpl * 4);
            asm volatile("st.shared.b32 [%0], %1;" :: "r"(sb + off), "r"(h) : "memory");
        }
    }

    // ---- B row-plane stage: plane row yy -> slot (yy+4)&3 ----
    auto stage_B = [&](int yy) {
        const int slot = (yy + 4) & 3;
        const bool ok_row = (yy >= 0) && (yy < HH);
        const uint32_t* src = in + ((size_t)b * 64 * HH + (ok_row ? yy : 0)) * WW;
        const int cpl = lane & 3, po = lane >> 2;
        const uint32_t bH = sb + OFF_B + slot * B_PLANE;
        const uint32_t bL = sb + OFF_B + (4 + slot) * B_PLANE;
        for (int it = warp; it < 136; it += NWARPS) {
            int c = it & 7, pxt = it >> 3;
            int px = pxt * 8 + po;
            if (px >= 132) continue;
            int ci0 = c * 8 + cpl * 2;
            int gx = x0 - 1 + px;
            bool ok = ok_row && (gx >= 0) && (gx < WW);
            const uint32_t* p = src + (size_t)ci0 * HWSZ + (ok ? gx : 0);
            uint32_t u0 = ok ? __ldg(p) : 0u;
            uint32_t u1 = ok ? __ldg(p + HWSZ) : 0u;
            uint32_t hi, lo;
            asm("prmt.b32 %0, %1, %2, 0x5410;" : "=r"(hi) : "r"(u0), "r"(u1));
            asm("prmt.b32 %0, %1, %2, 0x7632;" : "=r"(lo) : "r"(u0), "r"(u1));
            uint32_t off = (uint32_t)(px * 128 + ((c ^ (px & 7)) << 4) + cpl * 4);
            asm volatile("st.shared.b32 [%0], %1;" :: "r"(bH + off), "r"(hi) : "memory");
            asm volatile("st.shared.b32 [%0], %1;" :: "r"(bL + off), "r"(lo) : "memory");
        }
    };

    stage_B(y0 - 1);
    stage_B(y0);
    stage_B(y0 + 1);
    stage_B(y0 + 2);
    __syncthreads();

    const int r7 = lane & 7, g = lane >> 3;
    const int a_row = wy * 16 + r7 + ((g & 1) << 3);  // co row within 32
    const int a_kh = g >> 1;
    const int b_noff = r7;
    const int b_kh = g & 1;
    const int nb = wx * 8;
    const int row_d = lane >> 2, col_d = (lane & 3) * 2;

    const int yend = y0 + RPC;
#pragma unroll 1
    for (int y = y0; y < yend; y += 2) {
        float acc[2][4];
#pragma unroll
        for (int r = 0; r < 2; r++)
#pragma unroll
            for (int j = 0; j < 4; j++) acc[r][j] = 0.f;

        // plane slots: index i = input row (y-1+i), i=0..3
        uint32_t plH[4], plL[4];
#pragma unroll
        for (int i = 0; i < 4; i++) {
            int slot = (y - 1 + i + 4) & 3;
            plH[i] = sb + OFF_B + slot * B_PLANE;
            plL[i] = plH[i] + 4 * B_PLANE;
        }

#pragma unroll
        for (int kc = 0; kc < 4; kc++) {
#pragma unroll
            for (int dx = 0; dx < 3; dx++) {
                const int pxm = nb + dx + b_noff;
                const uint32_t bRow = (uint32_t)(pxm * 128);
                const uint32_t cB =
                    (uint32_t)((((kc << 1) | b_kh) ^ (pxm & 7)) << 4);
                // B n8 fragments for all 4 planes, hi+lo (8 LDSM.x2)
                uint32_t BF[4][2][2];
#pragma unroll
                for (int pl = 0; pl < 4; pl++) {
                    ldmx2(BF[pl][0][0], BF[pl][0][1], plH[pl] + bRow + cB);
                    ldmx2(BF[pl][1][0], BF[pl][1][1], plL[pl] + bRow + cB);
                }
                const uint32_t cA = (uint32_t)((((kc << 1) | a_kh) ^ r7) << 4);
#pragma unroll
                for (int dy = 0; dy < 3; dy++) {
                    const int t = dy * 3 + dx;
                    const uint32_t aHp = sb + (uint32_t)(t * 32 * 128);
                    uint32_t AH[4];
                    ldmx4(AH[0], AH[1], AH[2], AH[3],
                          aHp + (uint32_t)(a_row * 128) + cA);
                    // row 0 (y): plane dy; row 1 (y+1): plane dy+1
                    mma16816(acc[0], AH, BF[dy][0][0], BF[dy][0][1]);
                    mma16816(acc[0], AH, BF[dy][1][0], BF[dy][1][1]);
                    mma16816(acc[1], AH, BF[dy + 1][0][0], BF[dy + 1][0][1]);
                    mma16816(acc[1], AH, BF[dy + 1][1][0], BF[dy + 1][1][1]);
                }
            }
        }

        // epilogue (global only, no SMEM)
#pragma unroll
        for (int r = 0; r < 2; r++) {
            const int yy = y + r;
            float* c = acc[r];
            int x = x0 + nb + col_d;
#pragma unroll
            for (int h = 0; h < 2; h++) {
                int co = co_base + wy * 16 + row_d + h * 8;
                if (co < COUT) {
                    float bv = __ldg(bias + co);
                    float v0 = c[2 * h] + bv, v1 = c[2 * h + 1] + bv;
                    if (RELU) { v0 = fmaxf(v0, 0.f); v1 = fmaxf(v1, 0.f); }
                    size_t idx = (((size_t)b * COUT + co) * HH + yy) * WW + x;
                    if (PACK_OUT) {
                        uint2 u = make_uint2(pack_split(v0), pack_split(v1));
                        *reinterpret_cast<uint2*>((uint32_t*)outv + idx) = u;
                    } else {
                        *reinterpret_cast<float2*>((float*)outv + idx) =
                            make_float2(v0, v1);
                    }
                }
            }
        }

        if (y + 2 < yend) {
            __syncthreads();
            stage_B(y + 3);
            stage_B(y + 4);
            __syncthreads();
        }
    }
}

// ======================= scalar conv1 (4 -> 64) =============================
__device__ __forceinline__ unsigned long long pack2(float x, float y) {
    unsigned long long r;
    asm("mov.b64 %0, {%1, %2};" : "=l"(r) : "f"(x), "f"(y));
    return r;
}
__device__ __forceinline__ unsigned long long bcast2(float x) { return pack2(x, x); }
__device__ __forceinline__ float2 unpack2(unsigned long long v) {
    float2 f;
    asm("mov.b64 {%0, %1}, %2;" : "=f"(f.x), "=f"(f.y) : "l"(v));
    return f;
}
__device__ __forceinline__ unsigned long long ffma2(unsigned long long a,
                                                    unsigned long long b,
                                                    unsigned long long c) {
    unsigned long long d;
    asm("fma.rn.f32x2 %0, %1, %2, %3;" : "=l"(d) : "l"(a), "l"(b), "l"(c));
    return d;
}

__global__ __launch_bounds__(512, 1)
void conv1_kernel(const float* __restrict__ rgb, const float* __restrict__ depth,
                  const float* __restrict__ wgt, const float* __restrict__ bias,
                  uint32_t* __restrict__ out) {
    constexpr int QS = 16, PIX = 4, CCH = 4;
    constexpr int NP = 8, NP2 = 4;
    __shared__ __align__(16) float ws[CCH][9][4][QS];

    const int tid = threadIdx.x;
    const int lx = tid & 31;
    const int ty = (tid >> 5) & 3;
    const int q = tid >> 7;
    const int x = blockIdx.x * 32 + lx;
    const int y0 = blockIdx.y * (4 * PIX) + ty * PIX;
    const int b = blockIdx.z;
    const int co0 = q * QS;

    unsigned long long acc[PIX][NP];
#pragma unroll
    for (int pr = 0; pr < NP; pr++) {
        unsigned long long bb = pack2(__ldg(bias + co0 + 2 * pr),
                                      __ldg(bias + co0 + 2 * pr + 1));
#pragma unroll
        for (int p = 0; p < PIX; p++) acc[p][pr] = bb;
    }

    int rowoff[PIX + 2];
    bool rok[PIX + 2];
#pragma unroll
    for (int r = 0; r < PIX + 2; r++) {
        int yy = y0 - 1 + r;
        rok[r] = (yy >= 0) && (yy < HH);
        rowoff[r] = yy * WW;
    }
    const bool xok0 = (x > 0), xok2 = (x < WW - 1);

    for (int i = tid; i < CCH * 9 * 4 * QS; i += 512) {
        int col = i % QS;
        int qq = (i / QS) % 4;
        int t = (i / (QS * 4)) % 9;
        int cl = i / (QS * 4 * 9);
        (&ws[0][0][0][0])[i] = __ldg(wgt + ((size_t)(qq * QS + col) * 4 + cl) * 9 + t);
    }
    __syncthreads();

#pragma unroll
    for (int ci = 0; ci < 4; ci++) {
        const float* ip = (ci < 3) ? (rgb + ((size_t)b * 3 + ci) * HWSZ)
                                   : (depth + (size_t)b * HWSZ);
        const float* ipx = ip + x;
        float v[PIX + 2][3];
#pragma unroll
        for (int r = 0; r < PIX + 2; r++) {
            v[r][0] = (rok[r] && xok0) ? __ldg(ipx + rowoff[r] - 1) : 0.f;
            v[r][1] = rok[r] ? __ldg(ipx + rowoff[r]) : 0.f;
            v[r][2] = (rok[r] && xok2) ? __ldg(ipx + rowoff[r] + 1) : 0.f;
        }
#pragma unroll
        for (int dy = 0; dy < 3; dy++) {
#pragma unroll
            for (int dx = 0; dx < 3; dx++) {
                const ulonglong2* wp =
                    reinterpret_cast<const ulonglong2*>(&ws[ci][dy * 3 + dx][q][0]);
                ulonglong2 wq[NP2];
#pragma unroll
                for (int j = 0; j < NP2; j++) wq[j] = wp[j];
#pragma unroll
                for (int p = 0; p < PIX; p++) {
                    unsigned long long vv = bcast2(v[p + dy][dx]);
#pragma unroll
                    for (int j = 0; j < NP2; j++) {
                        acc[p][2 * j] = ffma2(vv, wq[j].x, acc[p][2 * j]);
                        acc[p][2 * j + 1] = ffma2(vv, wq[j].y, acc[p][2 * j + 1]);
                    }
                }
            }
        }
    }

#pragma unroll
    for (int p = 0; p < PIX; p++) {
        size_t base = ((size_t)b * 64) * HWSZ + (size_t)(y0 + p) * WW + x;
#pragma unroll
        for (int pr = 0; pr < NP; pr++) {
            float2 f = unpack2(acc[p][pr]);
            f.x = fmaxf(f.x, 0.f);
            f.y = fmaxf(f.y, 0.f);
            int co = co0 + 2 * pr;
            out[base + (size_t)co * HWSZ] = pack_split(f.x);
            out[base + (size_t)(co + 1) * HWSZ] = pack_split(f.y);
        }
    }
}

// ======================= softmax + bokeh ====================================
__global__ __launch_bounds__(128, 4)
void softmax_bokeh_kernel(const float* __restrict__ logits,
                          const float* __restrict__ rgb,
                          float* __restrict__ out) {
    __shared__ float tile[3][12][40];
    const int tid = threadIdx.x;
    const int lx = tid & 31;
    const int ty = tid >> 5;
    const int x = blockIdx.x * 32 + lx;
    const int y = blockIdx.y * 4 + ty;
    const int b = blockIdx.z;
    const int gx0 = blockIdx.x * 32 - 4;
    const int gy0 = blockIdx.y * 4 - 4;

    for (int i = tid; i < 3 * 12 * 40; i += 128) {
        int xx = i % 40;
        int yy = (i / 40) % 12;
        int c = i / 480;
        int gx = gx0 + xx, gy = gy0 + yy;
        float v = 0.f;
        if (gx >= 0 && gx < WW && gy >= 0 && gy < HH)
            v = rgb[((size_t)b * 3 + c) * HWSZ + (size_t)gy * WW + gx];
        tile[c][yy][xx] = v;
    }
    __syncthreads();

    float lg[81];
    const float* lp = logits + (size_t)b * 81 * HWSZ + (size_t)y * WW + x;
    float m = -1e30f;
#pragma unroll
    for (int t = 0; t < 81; t++) {
        lg[t] = __ldg(lp + (size_t)t * HWSZ);
        m = fmaxf(m, lg[t]);
    }
    float s = 0.f;
#pragma unroll
    for (int t = 0; t < 81; t++) {
        float e = __expf(lg[t] - m);
        lg[t] = e;
        s += e;
    }
    float inv = 1.f / s;

    float r = 0.f, g = 0.f, bl = 0.f;
#pragma unroll
    for (int dy = 0; dy < 9; dy++) {
#pragma unroll
        for (int dx = 0; dx < 9; dx++) {
            float f = lg[dy * 9 + dx] * inv;
            r += f * tile[0][ty + dy][lx + dx];
            g += f * tile[1][ty + dy][lx + dx];
            bl += f * tile[2][ty + dy][lx + dx];
        }
    }
    size_t ob = (size_t)b * 3 * HWSZ + (size_t)y * WW + x;
    out[ob] = r;
    out[ob + HWSZ] = g;
    out[ob + 2 * HWSZ] = bl;
}

// ======================= launch =============================================
extern "C" void kernel_launch(void* const* d_in, const int* in_sizes, int n_in,
                              void* d_out, int out_size) {
    const float* rgb   = (const float*)d_in[0];
    const float* depth = (const float*)d_in[1];
    const float* w1    = (const float*)d_in[2];
    const float* b1    = (const float*)d_in[3];
    const float* w2    = (const float*)d_in[4];
    const float* b2    = (const float*)d_in[5];
    const float* w3    = (const float*)d_in[6];
    const float* b3    = (const float*)d_in[7];
    float* out = (float*)d_out;

    uint32_t *h1, *h2;
    float* lg;
    cudaGetSymbolAddress((void**)&h1, g_h1);
    cudaGetSymbolAddress((void**)&h2, g_h2);
    cudaGetSymbolAddress((void**)&lg, g_logits);

    cudaFuncSetAttribute(conv3x3_hmma<64, 2, true, true>,
                         cudaFuncAttributeMaxDynamicSharedMemorySize, HMMA_SMEM);
    cudaFuncSetAttribute(conv3x3_hmma<81, 3, false, false>,
                         cudaFuncAttributeMaxDynamicSharedMemorySize, HMMA_SMEM);

    // conv1: scalar FFMA2, writes fp16-split h1
    conv1_kernel<<<dim3(WW / 32, HH / 16, BATCH), 512>>>(rgb, depth, w1, b1, h1);
    // conv2: HMMA implicit GEMM (2 co-slices of 32), split in / split out
    conv3x3_hmma<64, 2, true, true><<<dim3(WW / NPX, HH / RPC, 2 * BATCH),
                                      NTHREADS, HMMA_SMEM>>>(h1, w2, b2, h2);
    // conv3: HMMA implicit GEMM (3 co-slices of 32, 81 real), split in / f32 out
    conv3x3_hmma<81, 3, false, false><<<dim3(WW / NPX, HH / RPC, 3 * BATCH),
                                        NTHREADS, HMMA_SMEM>>>(h2, w3, b3, lg);
    // softmax + bokeh
    softmax_bokeh_kernel<<<dim3(WW / 32, HH / 4, BATCH), 128>>>(lg, rgb, out);
}

// round 12
// speedup vs baseline: 3.6574x; 1.3437x over previous
#include <cuda_runtime.h>
#include <cuda_fp16.h>
#include <cstdint>
#include <cstddef>

#define HH 384
#define WW 384
#define BATCH 4
#define HWSZ (HH * WW)

// h1/h2: plain fp16 activations, layout [b][c][y][x]
__device__ __half g_h1[(size_t)BATCH * 64 * HWSZ];
__device__ __half g_h2[(size_t)BATCH * 64 * HWSZ];
__device__ float  g_logits[(size_t)BATCH * 81 * HWSZ];

// =============================== helpers ====================================
__device__ __forceinline__ uint32_t smem_u32(const void* p) {
    uint32_t a;
    asm("{ .reg .u64 t; cvta.to.shared.u64 t, %1; cvt.u32.u64 %0, t; }"
        : "=r"(a) : "l"(p));
    return a;
}
__device__ __forceinline__ void ldmx4(uint32_t& r0, uint32_t& r1, uint32_t& r2,
                                      uint32_t& r3, uint32_t addr) {
    asm volatile("ldmatrix.sync.aligned.m8n8.x4.shared.b16 {%0,%1,%2,%3}, [%4];"
                 : "=r"(r0), "=r"(r1), "=r"(r2), "=r"(r3) : "r"(addr));
}
__device__ __forceinline__ void ldmx2(uint32_t& r0, uint32_t& r1, uint32_t addr) {
    asm volatile("ldmatrix.sync.aligned.m8n8.x2.shared.b16 {%0,%1}, [%2];"
                 : "=r"(r0), "=r"(r1) : "r"(addr));
}
__device__ __forceinline__ void mma16816(float* c, const uint32_t* a,
                                         uint32_t b0, uint32_t b1) {
    asm volatile(
        "mma.sync.aligned.m16n8k16.row.col.f32.f16.f16.f32 "
        "{%0,%1,%2,%3}, {%4,%5,%6,%7}, {%8,%9}, {%0,%1,%2,%3};"
        : "+f"(c[0]), "+f"(c[1]), "+f"(c[2]), "+f"(c[3])
        : "r"(a[0]), "r"(a[1]), "r"(a[2]), "r"(a[3]), "r"(b0), "r"(b1));
}
__device__ __forceinline__ uint32_t packh2(float f0, float f1) {
    uint32_t h;
    asm("cvt.rn.f16x2.f32 %0, %1, %2;" : "=r"(h) : "f"(f1), "f"(f0));
    return h;
}

// ===================== HMMA implicit-GEMM 3x3 conv ==========================
// Single-fp16 products: weights fp16, activations fp16. C = W*X.
// Per CTA: co-slice M=32, px-tile N=128, persist over RPC=32 rows (2 per iter).
// 1024 threads / 32 warps: warp = (wy 0..1: co-half of 16) x (wx 0..15: 8-px).
// A (weights, 9 taps) staged once; B (fp16 input) ring of 4 row-planes,
// layout [px][ci] fp16, 16B-chunk XOR swizzle. Loop nest (kc -> dx -> planes
// -> dy) shares B fragments between the two output rows.
#define RPC 32
#define NPX 128
#define A_PLANE (9 * 32 * 128)             // 36864 (fp16 weights)
#define OFF_B   A_PLANE
#define B_PLANE (132 * 128)                // 16896 per slot
#define HMMA_SMEM (OFF_B + 4 * B_PLANE)    // 104448
#define NTHREADS 1024
#define NWARPS 32

template <int COUT, int NSLICE, bool RELU, bool PACK_OUT>
__global__ __launch_bounds__(NTHREADS, 1)
void conv3x3_hmma(const __half* __restrict__ in, const float* __restrict__ wgt,
                  const float* __restrict__ bias, void* __restrict__ outv) {
    extern __shared__ __align__(128) char smem[];
    const uint32_t sb = smem_u32(smem);
    const int tid = threadIdx.x, warp = tid >> 5, lane = tid & 31;
    const int x0 = blockIdx.x * NPX;
    const int y0 = blockIdx.y * RPC;
    const int mslice = blockIdx.z % NSLICE;
    const int b = blockIdx.z / NSLICE;
    const int co_base = mslice * 32;
    const int wy = warp & 1;      // co half (16)
    const int wx = warp >> 1;     // px slice (8)

    // ---- stage A: 9 taps x 32 co x 64 ci fp16, swizzled [co][ci] ----
    {
        const int cpl = lane & 3, po = lane >> 2;
        for (int it = warp; it < 288; it += NWARPS) {
            int t = it / 32, r = it & 31;
            int cotile = r >> 3, c = r & 7;
            int co = cotile * 8 + po;
            int ci0 = c * 8 + cpl * 2;
            int cog = co_base + co;
            float f0 = 0.f, f1 = 0.f;
            if (cog < COUT) {
                const float* wp = wgt + ((size_t)cog * 64 + ci0) * 9 + t;
                f0 = __ldg(wp);
                f1 = __ldg(wp + 9);
            }
            uint32_t h = packh2(f0, f1);
            uint32_t off = (uint32_t)((t * 32 + co) * 128 +
                                      ((c ^ (co & 7)) << 4) + cpl * 4);
            asm volatile("st.shared.b32 [%0], %1;" :: "r"(sb + off), "r"(h) : "memory");
        }
    }

    // ---- B row-plane stage: plane row yy -> slot (yy+4)&3 ----
    auto stage_B = [&](int yy) {
        const int slot = (yy + 4) & 3;
        const bool ok_row = (yy >= 0) && (yy < HH);
        const unsigned short* src = reinterpret_cast<const unsigned short*>(
            in + ((size_t)b * 64 * HH + (ok_row ? yy : 0)) * WW);
        const int cpl = lane & 3, po = lane >> 2;
        const uint32_t bH = sb + OFF_B + slot * B_PLANE;
        for (int it = warp; it < 136; it += NWARPS) {
            int c = it & 7, pxt = it >> 3;
            int px = pxt * 8 + po;
            if (px >= 132) continue;
            int ci0 = c * 8 + cpl * 2;
            int gx = x0 - 1 + px;
            bool ok = ok_row && (gx >= 0) && (gx < WW);
            const unsigned short* p = src + (size_t)ci0 * HWSZ + (ok ? gx : 0);
            uint32_t s0 = ok ? (uint32_t)__ldg(p) : 0u;
            uint32_t s1 = ok ? (uint32_t)__ldg(p + HWSZ) : 0u;
            uint32_t hi = s0 | (s1 << 16);
            uint32_t off = (uint32_t)(px * 128 + ((c ^ (px & 7)) << 4) + cpl * 4);
            asm volatile("st.shared.b32 [%0], %1;" :: "r"(bH + off), "r"(hi) : "memory");
        }
    };

    stage_B(y0 - 1);
    stage_B(y0);
    stage_B(y0 + 1);
    stage_B(y0 + 2);
    __syncthreads();

    const int r7 = lane & 7, g = lane >> 3;
    const int a_row = wy * 16 + r7 + ((g & 1) << 3);  // co row within 32
    const int a_kh = g >> 1;
    const int b_noff = r7;
    const int b_kh = g & 1;
    const int nb = wx * 8;
    const int row_d = lane >> 2, col_d = (lane & 3) * 2;

    const int yend = y0 + RPC;
#pragma unroll 1
    for (int y = y0; y < yend; y += 2) {
        float acc[2][4];
#pragma unroll
        for (int r = 0; r < 2; r++)
#pragma unroll
            for (int j = 0; j < 4; j++) acc[r][j] = 0.f;

        // plane slots: index i = input row (y-1+i), i=0..3
        uint32_t plH[4];
#pragma unroll
        for (int i = 0; i < 4; i++) {
            int slot = (y - 1 + i + 4) & 3;
            plH[i] = sb + OFF_B + slot * B_PLANE;
        }

#pragma unroll
        for (int kc = 0; kc < 4; kc++) {
#pragma unroll
            for (int dx = 0; dx < 3; dx++) {
                const int pxm = nb + dx + b_noff;
                const uint32_t bRow = (uint32_t)(pxm * 128);
                const uint32_t cB =
                    (uint32_t)((((kc << 1) | b_kh) ^ (pxm & 7)) << 4);
                // B n8 fragments for all 4 planes (4 LDSM.x2)
                uint32_t BF[4][2];
#pragma unroll
                for (int pl = 0; pl < 4; pl++)
                    ldmx2(BF[pl][0], BF[pl][1], plH[pl] + bRow + cB);
                const uint32_t cA = (uint32_t)((((kc << 1) | a_kh) ^ r7) << 4);
#pragma unroll
                for (int dy = 0; dy < 3; dy++) {
                    const int t = dy * 3 + dx;
                    const uint32_t aHp = sb + (uint32_t)(t * 32 * 128);
                    uint32_t AH[4];
                    ldmx4(AH[0], AH[1], AH[2], AH[3],
                          aHp + (uint32_t)(a_row * 128) + cA);
                    // row 0 (y): plane dy; row 1 (y+1): plane dy+1
                    mma16816(acc[0], AH, BF[dy][0], BF[dy][1]);
                    mma16816(acc[1], AH, BF[dy + 1][0], BF[dy + 1][1]);
                }
            }
        }

        // epilogue (global only, no SMEM)
#pragma unroll
        for (int r = 0; r < 2; r++) {
            const int yy = y + r;
            float* c = acc[r];
            int x = x0 + nb + col_d;
#pragma unroll
            for (int h = 0; h < 2; h++) {
                int co = co_base + wy * 16 + row_d + h * 8;
                if (co < COUT) {
                    float bv = __ldg(bias + co);
                    float v0 = c[2 * h] + bv, v1 = c[2 * h + 1] + bv;
                    if (RELU) { v0 = fmaxf(v0, 0.f); v1 = fmaxf(v1, 0.f); }
                    size_t idx = (((size_t)b * COUT + co) * HH + yy) * WW + x;
                    if (PACK_OUT) {
                        __half2 hv = __floats2half2_rn(v0, v1);
                        *reinterpret_cast<__half2*>((__half*)outv + idx) = hv;
                    } else {
                        *reinterpret_cast<float2*>((float*)outv + idx) =
                            make_float2(v0, v1);
                    }
                }
            }
        }

        if (y + 2 < yend) {
            __syncthreads();
            stage_B(y + 3);
            stage_B(y + 4);
            __syncthreads();
        }
    }
}

// ======================= scalar conv1 (4 -> 64) =============================
__device__ __forceinline__ unsigned long long pack2(float x, float y) {
    unsigned long long r;
    asm("mov.b64 %0, {%1, %2};" : "=l"(r) : "f"(x), "f"(y));
    return r;
}
__device__ __forceinline__ unsigned long long bcast2(float x) { return pack2(x, x); }
__device__ __forceinline__ float2 unpack2(unsigned long long v) {
    float2 f;
    asm("mov.b64 {%0, %1}, %2;" : "=f"(f.x), "=f"(f.y) : "l"(v));
    return f;
}
__device__ __forceinline__ unsigned long long ffma2(unsigned long long a,
                                                    unsigned long long b,
                                                    unsigned long long c) {
    unsigned long long d;
    asm("fma.rn.f32x2 %0, %1, %2, %3;" : "=l"(d) : "l"(a), "l"(b), "l"(c));
    return d;
}

__global__ __launch_bounds__(512, 1)
void conv1_kernel(const float* __restrict__ rgb, const float* __restrict__ depth,
                  const float* __restrict__ wgt, const float* __restrict__ bias,
                  __half* __restrict__ out) {
    constexpr int QS = 16, PIX = 4, CCH = 4;
    constexpr int NP = 8, NP2 = 4;
    __shared__ __align__(16) float ws[CCH][9][4][QS];

    const int tid = threadIdx.x;
    const int lx = tid & 31;
    const int ty = (tid >> 5) & 3;
    const int q = tid >> 7;
    const int x = blockIdx.x * 32 + lx;
    const int y0 = blockIdx.y * (4 * PIX) + ty * PIX;
    const int b = blockIdx.z;
    const int co0 = q * QS;

    unsigned long long acc[PIX][NP];
#pragma unroll
    for (int pr = 0; pr < NP; pr++) {
        unsigned long long bb = pack2(__ldg(bias + co0 + 2 * pr),
                                      __ldg(bias + co0 + 2 * pr + 1));
#pragma unroll
        for (int p = 0; p < PIX; p++) acc[p][pr] = bb;
    }

    int rowoff[PIX + 2];
    bool rok[PIX + 2];
#pragma unroll
    for (int r = 0; r < PIX + 2; r++) {
        int yy = y0 - 1 + r;
        rok[r] = (yy >= 0) && (yy < HH);
        rowoff[r] = yy * WW;
    }
    const bool xok0 = (x > 0), xok2 = (x < WW - 1);

    for (int i = tid; i < CCH * 9 * 4 * QS; i += 512) {
        int col = i % QS;
        int qq = (i / QS) % 4;
        int t = (i / (QS * 4)) % 9;
        int cl = i / (QS * 4 * 9);
        (&ws[0][0][0][0])[i] = __ldg(wgt + ((size_t)(qq * QS + col) * 4 + cl) * 9 + t);
    }
    __syncthreads();

#pragma unroll
    for (int ci = 0; ci < 4; ci++) {
        const float* ip = (ci < 3) ? (rgb + ((size_t)b * 3 + ci) * HWSZ)
                                   : (depth + (size_t)b * HWSZ);
        const float* ipx = ip + x;
        float v[PIX + 2][3];
#pragma unroll
        for (int r = 0; r < PIX + 2; r++) {
            v[r][0] = (rok[r] && xok0) ? __ldg(ipx + rowoff[r] - 1) : 0.f;
            v[r][1] = rok[r] ? __ldg(ipx + rowoff[r]) : 0.f;
            v[r][2] = (rok[r] && xok2) ? __ldg(ipx + rowoff[r] + 1) : 0.f;
        }
#pragma unroll
        for (int dy = 0; dy < 3; dy++) {
#pragma unroll
            for (int dx = 0; dx < 3; dx++) {
                const ulonglong2* wp =
                    reinterpret_cast<const ulonglong2*>(&ws[ci][dy * 3 + dx][q][0]);
                ulonglong2 wq[NP2];
#pragma unroll
                for (int j = 0; j < NP2; j++) wq[j] = wp[j];
#pragma unroll
                for (int p = 0; p < PIX; p++) {
                    unsigned long long vv = bcast2(v[p + dy][dx]);
#pragma unroll
                    for (int j = 0; j < NP2; j++) {
                        acc[p][2 * j] = ffma2(vv, wq[j].x, acc[p][2 * j]);
                        acc[p][2 * j + 1] = ffma2(vv, wq[j].y, acc[p][2 * j + 1]);
                    }
                }
            }
        }
    }

#pragma unroll
    for (int p = 0; p < PIX; p++) {
        size_t base = ((size_t)b * 64) * HWSZ + (size_t)(y0 + p) * WW + x;
#pragma unroll
        for (int pr = 0; pr < NP; pr++) {
            float2 f = unpack2(acc[p][pr]);
            f.x = fmaxf(f.x, 0.f);
            f.y = fmaxf(f.y, 0.f);
            int co = co0 + 2 * pr;
            out[base + (size_t)co * HWSZ] = __float2half_rn(f.x);
            out[base + (size_t)(co + 1) * HWSZ] = __float2half_rn(f.y);
        }
    }
}

// ======================= softmax + bokeh ====================================
__global__ __launch_bounds__(128, 4)
void softmax_bokeh_kernel(const float* __restrict__ logits,
                          const float* __restrict__ rgb,
                          float* __restrict__ out) {
    __shared__ float tile[3][12][40];
    const int tid = threadIdx.x;
    const int lx = tid & 31;
    const int ty = tid >> 5;
    const int x = blockIdx.x * 32 + lx;
    const int y = blockIdx.y * 4 + ty;
    const int b = blockIdx.z;
    const int gx0 = blockIdx.x * 32 - 4;
    const int gy0 = blockIdx.y * 4 - 4;

    for (int i = tid; i < 3 * 12 * 40; i += 128) {
        int xx = i % 40;
        int yy = (i / 40) % 12;
        int c = i / 480;
        int gx = gx0 + xx, gy = gy0 + yy;
        float v = 0.f;
        if (gx >= 0 && gx < WW && gy >= 0 && gy < HH)
            v = rgb[((size_t)b * 3 + c) * HWSZ + (size_t)gy * WW + gx];
        tile[c][yy][xx] = v;
    }
    __syncthreads();

    float lg[81];
    const float* lp = logits + (size_t)b * 81 * HWSZ + (size_t)y * WW + x;
    float m = -1e30f;
#pragma unroll
    for (int t = 0; t < 81; t++) {
        lg[t] = __ldg(lp + (size_t)t * HWSZ);
        m = fmaxf(m, lg[t]);
    }
    float s = 0.f;
#pragma unroll
    for (int t = 0; t < 81; t++) {
        float e = __expf(lg[t] - m);
        lg[t] = e;
        s += e;
    }
    float inv = 1.f / s;

    float r = 0.f, g = 0.f, bl = 0.f;
#pragma unroll
    for (int dy = 0; dy < 9; dy++) {
#pragma unroll
        for (int dx = 0; dx < 9; dx++) {
            float f = lg[dy * 9 + dx] * inv;
            r += f * tile[0][ty + dy][lx + dx];
            g += f * tile[1][ty + dy][lx + dx];
            bl += f * tile[2][ty + dy][lx + dx];
        }
    }
    size_t ob = (size_t)b * 3 * HWSZ + (size_t)y * WW + x;
    out[ob] = r;
    out[ob + HWSZ] = g;
    out[ob + 2 * HWSZ] = bl;
}

// ======================= launch =============================================
extern "C" void kernel_launch(void* const* d_in, const int* in_sizes, int n_in,
                              void* d_out, int out_size) {
    const float* rgb   = (const float*)d_in[0];
    const float* depth = (const float*)d_in[1];
    const float* w1    = (const float*)d_in[2];
    const float* b1    = (const float*)d_in[3];
    const float* w2    = (const float*)d_in[4];
    const float* b2    = (const float*)d_in[5];
    const float* w3    = (const float*)d_in[6];
    const float* b3    = (const float*)d_in[7];
    float* out = (float*)d_out;

    __half *h1, *h2;
    float* lg;
    cudaGetSymbolAddress((void**)&h1, g_h1);
    cudaGetSymbolAddress((void**)&h2, g_h2);
    cudaGetSymbolAddress((void**)&lg, g_logits);

    cudaFuncSetAttribute(conv3x3_hmma<64, 2, true, true>,
                         cudaFuncAttributeMaxDynamicSharedMemorySize, HMMA_SMEM);
    cudaFuncSetAttribute(conv3x3_hmma<81, 3, false, false>,
                         cudaFuncAttributeMaxDynamicSharedMemorySize, HMMA_SMEM);

    // conv1: scalar FFMA2, writes fp16 h1
    conv1_kernel<<<dim3(WW / 32, HH / 16, BATCH), 512>>>(rgb, depth, w1, b1, h1);
    // conv2: HMMA implicit GEMM (2 co-slices of 32), fp16 in / fp16 out
    conv3x3_hmma<64, 2, true, true><<<dim3(WW / NPX, HH / RPC, 2 * BATCH),
                                      NTHREADS, HMMA_SMEM>>>(h1, w2, b2, h2);
    // conv3: HMMA implicit GEMM (3 co-slices of 32, 81 real), fp16 in / f32 out
    conv3x3_hmma<81, 3, false, false><<<dim3(WW / NPX, HH / RPC, 3 * BATCH),
                                        NTHREADS, HMMA_SMEM>>>(h2, w3, b3, lg);
    // softmax + bokeh
    softmax_bokeh_kernel<<<dim3(WW / 32, HH / 4, BATCH), 128>>>(lg, rgb, out);
}

// round 13
// speedup vs baseline: 4.2837x; 1.1712x over previous
#include <cuda_runtime.h>
#include <cuda_fp16.h>
#include <cstdint>
#include <cstddef>

#define HH 384
#define WW 384
#define BATCH 4
#define HWSZ (HH * WW)

// h1/h2: plain fp16 activations, layout [b][c][y][x]
__device__ __half g_h1[(size_t)BATCH * 64 * HWSZ];
__device__ __half g_h2[(size_t)BATCH * 64 * HWSZ];
__device__ float  g_logits[(size_t)BATCH * 81 * HWSZ];

// =============================== helpers ====================================
__device__ __forceinline__ uint32_t smem_u32(const void* p) {
    uint32_t a;
    asm("{ .reg .u64 t; cvta.to.shared.u64 t, %1; cvt.u32.u64 %0, t; }"
        : "=r"(a) : "l"(p));
    return a;
}
__device__ __forceinline__ void ldmx4(uint32_t& r0, uint32_t& r1, uint32_t& r2,
                                      uint32_t& r3, uint32_t addr) {
    asm volatile("ldmatrix.sync.aligned.m8n8.x4.shared.b16 {%0,%1,%2,%3}, [%4];"
                 : "=r"(r0), "=r"(r1), "=r"(r2), "=r"(r3) : "r"(addr));
}
__device__ __forceinline__ void ldmx2(uint32_t& r0, uint32_t& r1, uint32_t addr) {
    asm volatile("ldmatrix.sync.aligned.m8n8.x2.shared.b16 {%0,%1}, [%2];"
                 : "=r"(r0), "=r"(r1) : "r"(addr));
}
__device__ __forceinline__ void mma16816(float* c, const uint32_t* a,
                                         uint32_t b0, uint32_t b1) {
    asm volatile(
        "mma.sync.aligned.m16n8k16.row.col.f32.f16.f16.f32 "
        "{%0,%1,%2,%3}, {%4,%5,%6,%7}, {%8,%9}, {%0,%1,%2,%3};"
        : "+f"(c[0]), "+f"(c[1]), "+f"(c[2]), "+f"(c[3])
        : "r"(a[0]), "r"(a[1]), "r"(a[2]), "r"(a[3]), "r"(b0), "r"(b1));
}
__device__ __forceinline__ uint32_t packh2(float f0, float f1) {
    uint32_t h;
    asm("cvt.rn.f16x2.f32 %0, %1, %2;" : "=r"(h) : "f"(f1), "f"(f0));
    return h;
}

// ===================== HMMA implicit-GEMM 3x3 conv ==========================
// Single-fp16 products. Per CTA: co-slice M=32, px-tile N=128, RPC=32 rows,
// 4 rows per mainloop iteration over a 6-plane SMEM ring (rows y..y+3 share
// planes y-1..y+4; each B fragment feeds up to 4 rows).
// 1024 threads / 32 warps: warp = (wy 0..1: co-half of 16) x (wx 0..15: 8-px).
#define RPC 32
#define RPI 4
#define NPX 128
#define A_PLANE (9 * 32 * 128)             // 36864 (fp16 weights)
#define OFF_B   A_PLANE
#define B_PLANE (132 * 128)                // 16896 per slot
#define NSLOT 6
#define HMMA_SMEM (OFF_B + NSLOT * B_PLANE)  // 138240
#define NTHREADS 1024
#define NWARPS 32

template <int COUT, int NSLICE, bool RELU, bool PACK_OUT>
__global__ __launch_bounds__(NTHREADS, 1)
void conv3x3_hmma(const __half* __restrict__ in, const float* __restrict__ wgt,
                  const float* __restrict__ bias, void* __restrict__ outv) {
    extern __shared__ __align__(128) char smem[];
    const uint32_t sb = smem_u32(smem);
    const int tid = threadIdx.x, warp = tid >> 5, lane = tid & 31;
    const int x0 = blockIdx.x * NPX;
    const int y0 = blockIdx.y * RPC;
    const int mslice = blockIdx.z % NSLICE;
    const int b = blockIdx.z / NSLICE;
    const int co_base = mslice * 32;
    const int wy = warp & 1;      // co half (16)
    const int wx = warp >> 1;     // px slice (8)

    // ---- stage A: 9 taps x 32 co x 64 ci fp16, swizzled [co][ci] ----
    {
        const int cpl = lane & 3, po = lane >> 2;
        for (int it = warp; it < 288; it += NWARPS) {
            int t = it / 32, r = it & 31;
            int cotile = r >> 3, c = r & 7;
            int co = cotile * 8 + po;
            int ci0 = c * 8 + cpl * 2;
            int cog = co_base + co;
            float f0 = 0.f, f1 = 0.f;
            if (cog < COUT) {
                const float* wp = wgt + ((size_t)cog * 64 + ci0) * 9 + t;
                f0 = __ldg(wp);
                f1 = __ldg(wp + 9);
            }
            uint32_t h = packh2(f0, f1);
            uint32_t off = (uint32_t)((t * 32 + co) * 128 +
                                      ((c ^ (co & 7)) << 4) + cpl * 4);
            asm volatile("st.shared.b32 [%0], %1;" :: "r"(sb + off), "r"(h) : "memory");
        }
    }

    // ---- B row-plane stage: plane row yy -> slot (yy+NSLOT)%NSLOT ----
    auto stage_B = [&](int yy) {
        const int slot = (yy + NSLOT) % NSLOT;
        const bool ok_row = (yy >= 0) && (yy < HH);
        const unsigned short* src = reinterpret_cast<const unsigned short*>(
            in + ((size_t)b * 64 * HH + (ok_row ? yy : 0)) * WW);
        const int cpl = lane & 3, po = lane >> 2;
        const uint32_t bH = sb + OFF_B + slot * B_PLANE;
        for (int it = warp; it < 136; it += NWARPS) {
            int c = it & 7, pxt = it >> 3;
            int px = pxt * 8 + po;
            if (px >= 132) continue;
            int ci0 = c * 8 + cpl * 2;
            int gx = x0 - 1 + px;
            bool ok = ok_row && (gx >= 0) && (gx < WW);
            const unsigned short* p = src + (size_t)ci0 * HWSZ + (ok ? gx : 0);
            uint32_t s0 = ok ? (uint32_t)__ldg(p) : 0u;
            uint32_t s1 = ok ? (uint32_t)__ldg(p + HWSZ) : 0u;
            uint32_t hi = s0 | (s1 << 16);
            uint32_t off = (uint32_t)(px * 128 + ((c ^ (px & 7)) << 4) + cpl * 4);
            asm volatile("st.shared.b32 [%0], %1;" :: "r"(bH + off), "r"(hi) : "memory");
        }
    };

    // initial fill: planes y0-1 .. y0+4
    for (int i = -1; i <= 4; i++) stage_B(y0 + i);
    __syncthreads();

    const int r7 = lane & 7, g = lane >> 3;
    const int a_row = wy * 16 + r7 + ((g & 1) << 3);  // co row within 32
    const int a_kh = g >> 1;
    const int b_noff = r7;
    const int b_kh = g & 1;
    const int nb = wx * 8;
    const int row_d = lane >> 2, col_d = (lane & 3) * 2;

    const int yend = y0 + RPC;
#pragma unroll 1
    for (int y = y0; y < yend; y += RPI) {
        float acc[RPI][4];
#pragma unroll
        for (int r = 0; r < RPI; r++)
#pragma unroll
            for (int j = 0; j < 4; j++) acc[r][j] = 0.f;

        // plane slots: index i = input row (y-1+i), i=0..5
        uint32_t plH[NSLOT];
#pragma unroll
        for (int i = 0; i < NSLOT; i++)
            plH[i] = sb + OFF_B + ((y - 1 + i + NSLOT * 64) % NSLOT) * B_PLANE;

#pragma unroll
        for (int kc = 0; kc < 4; kc++) {
#pragma unroll
            for (int dx = 0; dx < 3; dx++) {
                const int pxm = nb + dx + b_noff;
                const uint32_t bRow = (uint32_t)(pxm * 128);
                const uint32_t cB =
                    (uint32_t)((((kc << 1) | b_kh) ^ (pxm & 7)) << 4);
                // B n8 fragments for all 6 planes (6 LDSM.x2)
                uint32_t BF[NSLOT][2];
#pragma unroll
                for (int pl = 0; pl < NSLOT; pl++)
                    ldmx2(BF[pl][0], BF[pl][1], plH[pl] + bRow + cB);
                const uint32_t cA = (uint32_t)((((kc << 1) | a_kh) ^ r7) << 4);
#pragma unroll
                for (int dy = 0; dy < 3; dy++) {
                    const int t = dy * 3 + dx;
                    const uint32_t aHp = sb + (uint32_t)(t * 32 * 128);
                    uint32_t AH[4];
                    ldmx4(AH[0], AH[1], AH[2], AH[3],
                          aHp + (uint32_t)(a_row * 128) + cA);
                    // row r uses plane (r + dy)
#pragma unroll
                    for (int r = 0; r < RPI; r++)
                        mma16816(acc[r], AH, BF[r + dy][0], BF[r + dy][1]);
                }
            }
        }

        // epilogue (global only, no SMEM)
#pragma unroll
        for (int r = 0; r < RPI; r++) {
            const int yy = y + r;
            float* c = acc[r];
            int x = x0 + nb + col_d;
#pragma unroll
            for (int h = 0; h < 2; h++) {
                int co = co_base + wy * 16 + row_d + h * 8;
                if (co < COUT) {
                    float bv = __ldg(bias + co);
                    float v0 = c[2 * h] + bv, v1 = c[2 * h + 1] + bv;
                    if (RELU) { v0 = fmaxf(v0, 0.f); v1 = fmaxf(v1, 0.f); }
                    size_t idx = (((size_t)b * COUT + co) * HH + yy) * WW + x;
                    if (PACK_OUT) {
                        __half2 hv = __floats2half2_rn(v0, v1);
                        *reinterpret_cast<__half2*>((__half*)outv + idx) = hv;
                    } else {
                        *reinterpret_cast<float2*>((float*)outv + idx) =
                            make_float2(v0, v1);
                    }
                }
            }
        }

        if (y + RPI < yend) {
            __syncthreads();
            stage_B(y + 5);
            stage_B(y + 6);
            stage_B(y + 7);
            stage_B(y + 8);
            __syncthreads();
        }
    }
}

// ======================= scalar conv1 (4 -> 64) =============================
__device__ __forceinline__ unsigned long long pack2(float x, float y) {
    unsigned long long r;
    asm("mov.b64 %0, {%1, %2};" : "=l"(r) : "f"(x), "f"(y));
    return r;
}
__device__ __forceinline__ unsigned long long bcast2(float x) { return pack2(x, x); }
__device__ __forceinline__ float2 unpack2(unsigned long long v) {
    float2 f;
    asm("mov.b64 {%0, %1}, %2;" : "=f"(f.x), "=f"(f.y) : "l"(v));
    return f;
}
__device__ __forceinline__ unsigned long long ffma2(unsigned long long a,
                                                    unsigned long long b,
                                                    unsigned long long c) {
    unsigned long long d;
    asm("fma.rn.f32x2 %0, %1, %2, %3;" : "=l"(d) : "l"(a), "l"(b), "l"(c));
    return d;
}

__global__ __launch_bounds__(512, 1)
void conv1_kernel(const float* __restrict__ rgb, const float* __restrict__ depth,
                  const float* __restrict__ wgt, const float* __restrict__ bias,
                  __half* __restrict__ out) {
    constexpr int QS = 16, PIX = 4, CCH = 4;
    constexpr int NP = 8, NP2 = 4;
    __shared__ __align__(16) float ws[CCH][9][4][QS];

    const int tid = threadIdx.x;
    const int lx = tid & 31;
    const int ty = (tid >> 5) & 3;
    const int q = tid >> 7;
    const int x = blockIdx.x * 32 + lx;
    const int y0 = blockIdx.y * (4 * PIX) + ty * PIX;
    const int b = blockIdx.z;
    const int co0 = q * QS;

    unsigned long long acc[PIX][NP];
#pragma unroll
    for (int pr = 0; pr < NP; pr++) {
        unsigned long long bb = pack2(__ldg(bias + co0 + 2 * pr),
                                      __ldg(bias + co0 + 2 * pr + 1));
#pragma unroll
        for (int p = 0; p < PIX; p++) acc[p][pr] = bb;
    }

    int rowoff[PIX + 2];
    bool rok[PIX + 2];
#pragma unroll
    for (int r = 0; r < PIX + 2; r++) {
        int yy = y0 - 1 + r;
        rok[r] = (yy >= 0) && (yy < HH);
        rowoff[r] = yy * WW;
    }
    const bool xok0 = (x > 0), xok2 = (x < WW - 1);

    for (int i = tid; i < CCH * 9 * 4 * QS; i += 512) {
        int col = i % QS;
        int qq = (i / QS) % 4;
        int t = (i / (QS * 4)) % 9;
        int cl = i / (QS * 4 * 9);
        (&ws[0][0][0][0])[i] = __ldg(wgt + ((size_t)(qq * QS + col) * 4 + cl) * 9 + t);
    }
    __syncthreads();

#pragma unroll
    for (int ci = 0; ci < 4; ci++) {
        const float* ip = (ci < 3) ? (rgb + ((size_t)b * 3 + ci) * HWSZ)
                                   : (depth + (size_t)b * HWSZ);
        const float* ipx = ip + x;
        float v[PIX + 2][3];
#pragma unroll
        for (int r = 0; r < PIX + 2; r++) {
            v[r][0] = (rok[r] && xok0) ? __ldg(ipx + rowoff[r] - 1) : 0.f;
            v[r][1] = rok[r] ? __ldg(ipx + rowoff[r]) : 0.f;
            v[r][2] = (rok[r] && xok2) ? __ldg(ipx + rowoff[r] + 1) : 0.f;
        }
#pragma unroll
        for (int dy = 0; dy < 3; dy++) {
#pragma unroll
            for (int dx = 0; dx < 3; dx++) {
                const ulonglong2* wp =
                    reinterpret_cast<const ulonglong2*>(&ws[ci][dy * 3 + dx][q][0]);
                ulonglong2 wq[NP2];
#pragma unroll
                for (int j = 0; j < NP2; j++) wq[j] = wp[j];
#pragma unroll
                for (int p = 0; p < PIX; p++) {
                    unsigned long long vv = bcast2(v[p + dy][dx]);
#pragma unroll
                    for (int j = 0; j < NP2; j++) {
                        acc[p][2 * j] = ffma2(vv, wq[j].x, acc[p][2 * j]);
                        acc[p][2 * j + 1] = ffma2(vv, wq[j].y, acc[p][2 * j + 1]);
                    }
                }
            }
        }
    }

#pragma unroll
    for (int p = 0; p < PIX; p++) {
        size_t base = ((size_t)b * 64) * HWSZ + (size_t)(y0 + p) * WW + x;
#pragma unroll
        for (int pr = 0; pr < NP; pr++) {
            float2 f = unpack2(acc[p][pr]);
            f.x = fmaxf(f.x, 0.f);
            f.y = fmaxf(f.y, 0.f);
            int co = co0 + 2 * pr;
            out[base + (size_t)co * HWSZ] = __float2half_rn(f.x);
            out[base + (size_t)(co + 1) * HWSZ] = __float2half_rn(f.y);
        }
    }
}

// ======================= softmax + bokeh ====================================
__global__ __launch_bounds__(128, 4)
void softmax_bokeh_kernel(const float* __restrict__ logits,
                          const float* __restrict__ rgb,
                          float* __restrict__ out) {
    __shared__ float tile[3][12][40];
    const int tid = threadIdx.x;
    const int lx = tid & 31;
    const int ty = tid >> 5;
    const int x = blockIdx.x * 32 + lx;
    const int y = blockIdx.y * 4 + ty;
    const int b = blockIdx.z;
    const int gx0 = blockIdx.x * 32 - 4;
    const int gy0 = blockIdx.y * 4 - 4;

    for (int i = tid; i < 3 * 12 * 40; i += 128) {
        int xx = i % 40;
        int yy = (i / 40) % 12;
        int c = i / 480;
        int gx = gx0 + xx, gy = gy0 + yy;
        float v = 0.f;
        if (gx >= 0 && gx < WW && gy >= 0 && gy < HH)
            v = rgb[((size_t)b * 3 + c) * HWSZ + (size_t)gy * WW + gx];
        tile[c][yy][xx] = v;
    }
    __syncthreads();

    float lg[81];
    const float* lp = logits + (size_t)b * 81 * HWSZ + (size_t)y * WW + x;
    float m = -1e30f;
#pragma unroll
    for (int t = 0; t < 81; t++) {
        lg[t] = __ldg(lp + (size_t)t * HWSZ);
        m = fmaxf(m, lg[t]);
    }
    float s = 0.f;
#pragma unroll
    for (int t = 0; t < 81; t++) {
        float e = __expf(lg[t] - m);
        lg[t] = e;
        s += e;
    }
    float inv = 1.f / s;

    float r = 0.f, g = 0.f, bl = 0.f;
#pragma unroll
    for (int dy = 0; dy < 9; dy++) {
#pragma unroll
        for (int dx = 0; dx < 9; dx++) {
            float f = lg[dy * 9 + dx] * inv;
            r += f * tile[0][ty + dy][lx + dx];
            g += f * tile[1][ty + dy][lx + dx];
            bl += f * tile[2][ty + dy][lx + dx];
        }
    }
    size_t ob = (size_t)b * 3 * HWSZ + (size_t)y * WW + x;
    out[ob] = r;
    out[ob + HWSZ] = g;
    out[ob + 2 * HWSZ] = bl;
}

// ======================= launch =============================================
extern "C" void kernel_launch(void* const* d_in, const int* in_sizes, int n_in,
                              void* d_out, int out_size) {
    const float* rgb   = (const float*)d_in[0];
    const float* depth = (const float*)d_in[1];
    const float* w1    = (const float*)d_in[2];
    const float* b1    = (const float*)d_in[3];
    const float* w2    = (const float*)d_in[4];
    const float* b2    = (const float*)d_in[5];
    const float* w3    = (const float*)d_in[6];
    const float* b3    = (const float*)d_in[7];
    float* out = (float*)d_out;

    __half *h1, *h2;
    float* lg;
    cudaGetSymbolAddress((void**)&h1, g_h1);
    cudaGetSymbolAddress((void**)&h2, g_h2);
    cudaGetSymbolAddress((void**)&lg, g_logits);

    cudaFuncSetAttribute(conv3x3_hmma<64, 2, true, true>,
                         cudaFuncAttributeMaxDynamicSharedMemorySize, HMMA_SMEM);
    cudaFuncSetAttribute(conv3x3_hmma<81, 3, false, false>,
                         cudaFuncAttributeMaxDynamicSharedMemorySize, HMMA_SMEM);

    // conv1: scalar FFMA2, writes fp16 h1
    conv1_kernel<<<dim3(WW / 32, HH / 16, BATCH), 512>>>(rgb, depth, w1, b1, h1);
    // conv2: HMMA implicit GEMM (2 co-slices of 32), fp16 in / fp16 out
    conv3x3_hmma<64, 2, true, true><<<dim3(WW / NPX, HH / RPC, 2 * BATCH),
                                      NTHREADS, HMMA_SMEM>>>(h1, w2, b2, h2);
    // conv3: HMMA implicit GEMM (3 co-slices of 32, 81 real), fp16 in / f32 out
    conv3x3_hmma<81, 3, false, false><<<dim3(WW / NPX, HH / RPC, 3 * BATCH),
                                        NTHREADS, HMMA_SMEM>>>(h2, w3, b3, lg);
    // softmax + bokeh
    softmax_bokeh_kernel<<<dim3(WW / 32, HH / 4, BATCH), 128>>>(lg, rgb, out);
}